// round 7
// baseline (speedup 1.0000x reference)
#include <cuda_runtime.h>
#include <cuda_bf16.h>
#include <cstdint>

#define BB 4
#define LL 512
#define DD 768
#define WW 12
#define TWOD 1536
#define THREED 2304
#define BL 2048
#define MOUT 24576
#define WD 9216

// ---- scratch (device globals; no allocation allowed) ----
__device__ __align__(16) __nv_bfloat16 g_hh[(long)BL*DD],      g_hl[(long)BL*DD];
__device__ __align__(16) __nv_bfloat16 g_pwh[(long)TWOD*DD],   g_pwl[(long)TWOD*DD];
__device__ __align__(16) __nv_bfloat16 g_owh[(long)DD*THREED], g_owl[(long)DD*THREED];
__device__ __align__(16) __nv_bfloat16 g_cwth[(long)WD*DD],    g_cwtl[(long)WD*DD];
__device__ __align__(16) __nv_bfloat16 g_ph[(long)BL*TWOD],    g_pl[(long)BL*TWOD];
__device__ __align__(16) float         g_G[(long)BL*WD];
__device__ __align__(16) __nv_bfloat16 g_ch[(long)MOUT*DD],    g_cl[(long)MOUT*DD];
__device__ __align__(16) float         g_SA[(long)BL*DD],      g_SB[(long)BL*DD];
__device__ int g_is64;

// ---- PTX helpers (baseline ISA only: sm_80-class ops, valid on compute_103) ----
__device__ __forceinline__ uint32_t smem_u32(const void* p) {
    uint32_t a;
    asm("{ .reg .u64 t; cvta.to.shared.u64 t, %1; cvt.u32.u64 %0, t; }" : "=r"(a) : "l"(p));
    return a;
}
__device__ __forceinline__ void cp16(uint32_t dst, const void* src) {
    asm volatile("cp.async.cg.shared.global [%0], [%1], 16;" :: "r"(dst), "l"(src));
}
#define CP_COMMIT() asm volatile("cp.async.commit_group;" ::: "memory")
#define CP_WAIT1()  asm volatile("cp.async.wait_group 1;" ::: "memory")

#define LDSM4(r, addr) \
    asm volatile("ldmatrix.sync.aligned.m8n8.x4.shared.b16 {%0,%1,%2,%3}, [%4];" \
        : "=r"((r)[0]), "=r"((r)[1]), "=r"((r)[2]), "=r"((r)[3]) : "r"(addr))

#define MMA16816(acc, a, b0, b1) \
    asm volatile("mma.sync.aligned.m16n8k16.row.col.f32.bf16.bf16.f32 " \
        "{%0,%1,%2,%3}, {%4,%5,%6,%7}, {%8,%9}, {%0,%1,%2,%3};" \
        : "+f"((acc)[0]), "+f"((acc)[1]), "+f"((acc)[2]), "+f"((acc)[3]) \
        : "r"((a)[0]), "r"((a)[1]), "r"((a)[2]), "r"((a)[3]), "r"(b0), "r"(b1))

// ---------------------------------------------------------------------------
__global__ void detect_idx_kernel(const int* __restrict__ p, int nwords) {
    __shared__ int any;
    if (threadIdx.x == 0) any = 0;
    __syncthreads();
    int found = 0;
    for (int i = threadIdx.x; 2 * i + 1 < nwords; i += blockDim.x)
        found |= (p[2 * i + 1] != 0);
    if (found) atomicOr(&any, 1);
    __syncthreads();
    if (threadIdx.x == 0) g_is64 = (any == 0) ? 1 : 0;
}

__global__ void split_kernel(const float* __restrict__ x,
                             __nv_bfloat16* __restrict__ xh,
                             __nv_bfloat16* __restrict__ xl, long n) {
    long i = (long)blockIdx.x * blockDim.x + threadIdx.x;
    if (i >= n) return;
    float v = x[i];
    __nv_bfloat16 h = __float2bfloat16(v);
    xh[i] = h;
    xl[i] = __float2bfloat16(v - __bfloat162float(h));
}

// conv_w [o,c,k] -> cwt [k*DD+o][c] bf16 hi/lo
__global__ void transpose_cw_kernel(const float* __restrict__ cw,
                                    __nv_bfloat16* __restrict__ th,
                                    __nv_bfloat16* __restrict__ tl) {
    int idx = blockIdx.x * blockDim.x + threadIdx.x;
    if (idx >= DD * DD) return;
    int o = idx / DD, c = idx % DD;
    const float* src = cw + (long)idx * WW;
#pragma unroll
    for (int k = 0; k < WW; k++) {
        float v = src[k];
        __nv_bfloat16 h = __float2bfloat16(v);
        long off = ((long)k * DD + o) * DD + c;
        th[off] = h;
        tl[off] = __float2bfloat16(v - __bfloat162float(h));
    }
}

// shifted cumsum of G + relu -> bf16 hi/lo
__global__ void cumsum_relu_kernel(const float* __restrict__ G,
                                   __nv_bfloat16* __restrict__ ch,
                                   __nv_bfloat16* __restrict__ cl) {
    long id = (long)blockIdx.x * blockDim.x + threadIdx.x;
    if (id >= (long)BL * DD) return;
    int o  = (int)(id % DD);
    int bl = (int)(id / DD);
    int l  = bl % LL;
    int bt = bl - l;
    float s = 0.f;
#pragma unroll
    for (int k = 0; k < WW; k++) {
        int t = l + k;
        if (t < LL) s += G[((long)(bt + t) * WW + k) * DD + o];
        float v = fmaxf(s, 0.f);
        __nv_bfloat16 h = __float2bfloat16(v);
        long off = ((long)bl * WW + k) * DD + o;
        ch[off] = h;
        cl[off] = __float2bfloat16(v - __bfloat162float(h));
    }
}

// ---------------------------------------------------------------------------
// bf16 split GEMM via mma.sync:  C[m,n] = sum_k (Ah+Al)[m,k]*(Bh+Bl)[n,k]
// 3-term compensation: AhBh + AhBl + AlBh, fp32 accumulators.
// CTA tile 128x128, BK=32, 8 warps (2M x 4N), warp tile 64x32.
// smem: 4 tiles (Ah,Al,Bh,Bl) of 128 rows x 80B (32 bf16 padded), double-buffered.
#define ROWB 80
#define TILEB (128*ROWB)     // 10240
#define STAGEB (4*TILEB)     // 40960
#define SMEMB (2*STAGEB)     // 81920

template <int EPI>
__global__ __launch_bounds__(256)
void gemm_mma(const __nv_bfloat16* __restrict__ Ah, const __nv_bfloat16* __restrict__ Al, int lda,
              const __nv_bfloat16* __restrict__ Bh, const __nv_bfloat16* __restrict__ Bl, int ldb,
              float* __restrict__ C, __nv_bfloat16* __restrict__ Chi, __nv_bfloat16* __restrict__ Clo,
              int ldc, int K,
              const float* __restrict__ bias,
              const float* __restrict__ SA, const float* __restrict__ SB,
              const int* __restrict__ span32) {
    extern __shared__ char smem[];
    const uint32_t sbase = smem_u32(smem);
    const int tid = threadIdx.x, lane = tid & 31, wid = tid >> 5;
    const int wm = wid & 1, wn = wid >> 1;           // 2 x 4 warp grid
    const int m0 = blockIdx.y * 128, n0 = blockIdx.x * 128;
    const int NIT = K >> 5;

    const char* gA[4] = {
        (const char*)(Ah + (long)m0 * lda), (const char*)(Al + (long)m0 * lda),
        (const char*)(Bh + (long)n0 * ldb), (const char*)(Bl + (long)n0 * ldb) };
    const long ldbytes[4] = { (long)lda * 2, (long)lda * 2, (long)ldb * 2, (long)ldb * 2 };

    // each thread: per tile, 2 chunks of 16B (512 chunks / 256 threads)
    const int r0c = tid >> 2, kc0 = tid & 3;          // chunk tid
    const int r1c = (tid + 256) >> 2, kc1 = tid & 3;  // chunk tid+256

    auto issue_load = [&](int it) {
        const int k0b = (it << 5) * 2;                // k-offset in bytes
        const uint32_t st = sbase + (it & 1) * STAGEB;
#pragma unroll
        for (int t = 0; t < 4; t++) {
            cp16(st + t * TILEB + r0c * ROWB + kc0 * 16, gA[t] + (long)r0c * ldbytes[t] + k0b + kc0 * 16);
            cp16(st + t * TILEB + r1c * ROWB + kc1 * 16, gA[t] + (long)r1c * ldbytes[t] + k0b + kc1 * 16);
        }
    };

    float acc[4][4][4];
#pragma unroll
    for (int i = 0; i < 4; i++)
#pragma unroll
        for (int j = 0; j < 4; j++)
#pragma unroll
            for (int v = 0; v < 4; v++) acc[i][j][v] = 0.f;

    issue_load(0);
    CP_COMMIT();

    const uint32_t a_lane_off = (uint32_t)((wm * 64 + (lane & 15)) * ROWB + (lane >> 4) * 16);
    const uint32_t b_lane_off = (uint32_t)((wn * 32 + (lane & 15)) * ROWB + (lane >> 4) * 16);

    for (int it = 0; it < NIT; it++) {
        if (it + 1 < NIT) issue_load(it + 1);
        CP_COMMIT();
        CP_WAIT1();
        __syncthreads();

        const uint32_t st = sbase + (it & 1) * STAGEB;
#pragma unroll
        for (int ks = 0; ks < 2; ks++) {
            uint32_t ah[4][4], al[4][4];
#pragma unroll
            for (int mt = 0; mt < 4; mt++) {
                uint32_t addr = st + a_lane_off + mt * 16 * ROWB + ks * 32;
                LDSM4(ah[mt], addr);
                LDSM4(al[mt], addr + TILEB);
            }
            uint32_t bh[2][4], bl[2][4];
#pragma unroll
            for (int nb = 0; nb < 2; nb++) {
                uint32_t addr = st + 2 * TILEB + b_lane_off + nb * 16 * ROWB + ks * 32;
                LDSM4(bh[nb], addr);
                LDSM4(bl[nb], addr + TILEB);
            }
#pragma unroll
            for (int mt = 0; mt < 4; mt++)
#pragma unroll
                for (int nt = 0; nt < 4; nt++) {
                    const int nb = nt >> 1, sel = nt & 1;
                    MMA16816(acc[mt][nt], ah[mt], bh[nb][sel], bh[nb][sel + 2]);
                    MMA16816(acc[mt][nt], ah[mt], bl[nb][sel], bl[nb][sel + 2]);
                    MMA16816(acc[mt][nt], al[mt], bh[nb][sel], bh[nb][sel + 2]);
                }
        }
        __syncthreads();
    }

    // ---- epilogue ----
    const int qrow = lane >> 2, qcol = (lane & 3) * 2;
    const int is64 = (EPI == 2) ? g_is64 : 0;

#pragma unroll
    for (int mt = 0; mt < 4; mt++) {
        const int r0 = m0 + wm * 64 + mt * 16 + qrow;
        const int r1 = r0 + 8;

        int sw0 = 0, ew0 = 0, sw1 = 0, ew1 = 0, boff = 0;
        const float *sa0 = nullptr, *sb0 = nullptr, *sa1 = nullptr, *sb1 = nullptr;
        if (EPI == 2) {
            if (is64) {
                sw0 = span32[(long)r0 * 4]; ew0 = span32[(long)r0 * 4 + 2];
                sw1 = span32[(long)r1 * 4]; ew1 = span32[(long)r1 * 4 + 2];
            } else {
                sw0 = span32[(long)r0 * 2]; ew0 = span32[(long)r0 * 2 + 1];
                sw1 = span32[(long)r1 * 2]; ew1 = span32[(long)r1 * 2 + 1];
            }
            sw0 = min(max(sw0, 0), LL - 1); ew0 = min(max(ew0, 0), LL - 1);
            sw1 = min(max(sw1, 0), LL - 1); ew1 = min(max(ew1, 0), LL - 1);
            boff = (r0 / (LL * WW)) * LL;   // r0, r1 always in same batch (16 | LL*WW)
            sa0 = SA + (long)(boff + sw0) * DD; sb0 = SB + (long)(boff + ew0) * DD;
            sa1 = SA + (long)(boff + sw1) * DD; sb1 = SB + (long)(boff + ew1) * DD;
        }

#pragma unroll
        for (int nt = 0; nt < 4; nt++) {
            const int gc = n0 + wn * 32 + nt * 8 + qcol;
            const float* a = acc[mt][nt];
            if (EPI == 0) {
                *(float2*)(C + (long)r0 * ldc + gc) = make_float2(a[0], a[1]);
                *(float2*)(C + (long)r1 * ldc + gc) = make_float2(a[2], a[3]);
            } else if (EPI == 1) {
                float2 b = *(const float2*)(bias + gc);
                float v0 = fmaxf(a[0] + b.x, 0.f), v1 = fmaxf(a[1] + b.y, 0.f);
                float v2 = fmaxf(a[2] + b.x, 0.f), v3 = fmaxf(a[3] + b.y, 0.f);
                __nv_bfloat162 h01 = __floats2bfloat162_rn(v0, v1);
                __nv_bfloat162 h23 = __floats2bfloat162_rn(v2, v3);
                __nv_bfloat162 l01 = __floats2bfloat162_rn(v0 - __bfloat162float(h01.x),
                                                           v1 - __bfloat162float(h01.y));
                __nv_bfloat162 l23 = __floats2bfloat162_rn(v2 - __bfloat162float(h23.x),
                                                           v3 - __bfloat162float(h23.y));
                *(__nv_bfloat162*)(Chi + (long)r0 * ldc + gc) = h01;
                *(__nv_bfloat162*)(Chi + (long)r1 * ldc + gc) = h23;
                *(__nv_bfloat162*)(Clo + (long)r0 * ldc + gc) = l01;
                *(__nv_bfloat162*)(Clo + (long)r1 * ldc + gc) = l23;
            } else {
                float2 b  = *(const float2*)(bias + gc);
                float2 s0 = *(const float2*)(sa0 + gc), e0 = *(const float2*)(sb0 + gc);
                float2 s1 = *(const float2*)(sa1 + gc), e1 = *(const float2*)(sb1 + gc);
                float2 o0 = make_float2(fmaxf(a[0] + s0.x + e0.x + b.x, 0.f),
                                        fmaxf(a[1] + s0.y + e0.y + b.y, 0.f));
                float2 o1 = make_float2(fmaxf(a[2] + s1.x + e1.x + b.x, 0.f),
                                        fmaxf(a[3] + s1.y + e1.y + b.y, 0.f));
                *(float2*)(C + (long)r0 * ldc + gc) = o0;
                *(float2*)(C + (long)r1 * ldc + gc) = o1;
            }
        }
    }
}

// ---------------------------------------------------------------------------
extern "C" void kernel_launch(void* const* d_in, const int* in_sizes, int n_in,
                              void* d_out, int out_size) {
    const float* h      = (const float*)d_in[0];
    const int*   span32 = (const int*)d_in[1];
    const float* proj_w = (const float*)d_in[2];
    const float* proj_b = (const float*)d_in[3];
    const float* conv_w = (const float*)d_in[4];
    const float* out_w  = (const float*)d_in[5];
    const float* out_b  = (const float*)d_in[6];
    float*       out    = (float*)d_out;

    __nv_bfloat16 *hh, *hl, *pwh, *pwl, *owh, *owl, *cwth, *cwtl, *ph, *pl, *ch, *cl;
    float *G, *SA, *SB;
    cudaGetSymbolAddress((void**)&hh,   g_hh);   cudaGetSymbolAddress((void**)&hl,   g_hl);
    cudaGetSymbolAddress((void**)&pwh,  g_pwh);  cudaGetSymbolAddress((void**)&pwl,  g_pwl);
    cudaGetSymbolAddress((void**)&owh,  g_owh);  cudaGetSymbolAddress((void**)&owl,  g_owl);
    cudaGetSymbolAddress((void**)&cwth, g_cwth); cudaGetSymbolAddress((void**)&cwtl, g_cwtl);
    cudaGetSymbolAddress((void**)&ph,   g_ph);   cudaGetSymbolAddress((void**)&pl,   g_pl);
    cudaGetSymbolAddress((void**)&ch,   g_ch);   cudaGetSymbolAddress((void**)&cl,   g_cl);
    cudaGetSymbolAddress((void**)&G,    g_G);
    cudaGetSymbolAddress((void**)&SA,   g_SA);   cudaGetSymbolAddress((void**)&SB,   g_SB);

    cudaFuncSetAttribute((const void*)gemm_mma<0>, cudaFuncAttributeMaxDynamicSharedMemorySize, SMEMB);
    cudaFuncSetAttribute((const void*)gemm_mma<1>, cudaFuncAttributeMaxDynamicSharedMemorySize, SMEMB);
    cudaFuncSetAttribute((const void*)gemm_mma<2>, cudaFuncAttributeMaxDynamicSharedMemorySize, SMEMB);

    // 0. span_idx dtype detection (device-side, capturable)
    detect_idx_kernel<<<1, 256>>>(span32, BB * LL * WW * 2);

    // 1. fp32 -> bf16 hi/lo conversions
    split_kernel<<<((long)BL * DD + 255) / 256, 256>>>(h, hh, hl, (long)BL * DD);
    split_kernel<<<((long)TWOD * DD + 255) / 256, 256>>>(proj_w, pwh, pwl, (long)TWOD * DD);
    split_kernel<<<((long)DD * THREED + 255) / 256, 256>>>(out_w, owh, owl, (long)DD * THREED);
    transpose_cw_kernel<<<(DD * DD + 255) / 256, 256>>>(conv_w, cwth, cwtl);

    // 2. prelu = relu(h @ proj_w^T + proj_b) -> bf16 hi/lo   [BL, 2D]
    gemm_mma<1><<<dim3(TWOD / 128, BL / 128), 256, SMEMB>>>(
        hh, hl, DD, pwh, pwl, DD, nullptr, ph, pl, TWOD, DD, proj_b, nullptr, nullptr, nullptr);

    // 3. G = h @ cwt^T  (fp32)                               [BL, W*D]
    gemm_mma<0><<<dim3(WD / 128, BL / 128), 256, SMEMB>>>(
        hh, hl, DD, cwth, cwtl, DD, G, nullptr, nullptr, WD, DD, nullptr, nullptr, nullptr, nullptr);

    // 4. SA = prelu[:, :D] @ out_w[:, :D]^T                  [BL, D]
    gemm_mma<0><<<dim3(DD / 128, BL / 128), 256, SMEMB>>>(
        ph, pl, TWOD, owh, owl, THREED, SA, nullptr, nullptr, DD, DD,
        nullptr, nullptr, nullptr, nullptr);

    // 5. SB = prelu[:, D:] @ out_w[:, D:2D]^T                [BL, D]
    gemm_mma<0><<<dim3(DD / 128, BL / 128), 256, SMEMB>>>(
        ph + DD, pl + DD, TWOD, owh + DD, owl + DD, THREED, SB, nullptr, nullptr, DD, DD,
        nullptr, nullptr, nullptr, nullptr);

    // 6. convrelu = relu(shifted cumsum of G) -> bf16 hi/lo  [M_out, D]
    cumsum_relu_kernel<<<((long)BL * DD + 255) / 256, 256>>>(G, ch, cl);

    // 7. out = relu(conv @ out_w[:,2D:]^T + gather(SA) + gather(SB) + out_b)
    gemm_mma<2><<<dim3(DD / 128, MOUT / 128), 256, SMEMB>>>(
        ch, cl, DD, owh + TWOD, owl + TWOD, THREED, out, nullptr, nullptr, DD, DD,
        out_b, SA, SB, span32);
}

// round 8
// speedup vs baseline: 1.0005x; 1.0005x over previous
#include <cuda_runtime.h>
#include <cuda_bf16.h>
#include <cstdint>

#define BB 4
#define LL 512
#define DD 768
#define WW 12
#define TWOD 1536
#define THREED 2304
#define BL 2048
#define MOUT 24576
#define WD 9216

// ---- scratch (device globals; no allocation allowed) ----
__device__ __align__(16) __nv_bfloat16 g_hh[(long)BL*DD],      g_hl[(long)BL*DD];
__device__ __align__(16) __nv_bfloat16 g_pwh[(long)TWOD*DD],   g_pwl[(long)TWOD*DD];
__device__ __align__(16) __nv_bfloat16 g_owh[(long)DD*THREED], g_owl[(long)DD*THREED];
__device__ __align__(16) __nv_bfloat16 g_cwth[(long)WD*DD],    g_cwtl[(long)WD*DD];
__device__ __align__(16) __nv_bfloat16 g_ph[(long)BL*TWOD],    g_pl[(long)BL*TWOD];
__device__ __align__(16) float         g_G[(long)BL*WD];
__device__ __align__(16) __nv_bfloat16 g_ch[(long)MOUT*DD],    g_cl[(long)MOUT*DD];
__device__ __align__(16) float         g_SA[(long)BL*DD],      g_SB[(long)BL*DD];
__device__ int g_is64;

// ---- PTX helpers (baseline ISA only: sm_80-class ops, valid on compute_103) ----
__device__ __forceinline__ uint32_t smem_u32(const void* p) {
    uint32_t a;
    asm("{ .reg .u64 t; cvta.to.shared.u64 t, %1; cvt.u32.u64 %0, t; }" : "=r"(a) : "l"(p));
    return a;
}
__device__ __forceinline__ void cp16(uint32_t dst, const void* src) {
    asm volatile("cp.async.cg.shared.global [%0], [%1], 16;" :: "r"(dst), "l"(src));
}
#define CP_COMMIT() asm volatile("cp.async.commit_group;" ::: "memory")
#define CP_WAIT1()  asm volatile("cp.async.wait_group 1;" ::: "memory")

#define LDSM4(r, addr) \
    asm volatile("ldmatrix.sync.aligned.m8n8.x4.shared.b16 {%0,%1,%2,%3}, [%4];" \
        : "=r"((r)[0]), "=r"((r)[1]), "=r"((r)[2]), "=r"((r)[3]) : "r"(addr))

#define MMA16816(acc, a, b0, b1) \
    asm volatile("mma.sync.aligned.m16n8k16.row.col.f32.bf16.bf16.f32 " \
        "{%0,%1,%2,%3}, {%4,%5,%6,%7}, {%8,%9}, {%0,%1,%2,%3};" \
        : "+f"((acc)[0]), "+f"((acc)[1]), "+f"((acc)[2]), "+f"((acc)[3]) \
        : "r"((a)[0]), "r"((a)[1]), "r"((a)[2]), "r"((a)[3]), "r"(b0), "r"(b1))

// ---------------------------------------------------------------------------
__global__ void detect_idx_kernel(const int* __restrict__ p, int nwords) {
    __shared__ int any;
    if (threadIdx.x == 0) any = 0;
    __syncthreads();
    int found = 0;
    for (int i = threadIdx.x; 2 * i + 1 < nwords; i += blockDim.x)
        found |= (p[2 * i + 1] != 0);
    if (found) atomicOr(&any, 1);
    __syncthreads();
    if (threadIdx.x == 0) g_is64 = (any == 0) ? 1 : 0;
}

__global__ void split_kernel(const float* __restrict__ x,
                             __nv_bfloat16* __restrict__ xh,
                             __nv_bfloat16* __restrict__ xl, long n) {
    long i = (long)blockIdx.x * blockDim.x + threadIdx.x;
    if (i >= n) return;
    float v = x[i];
    __nv_bfloat16 h = __float2bfloat16(v);
    xh[i] = h;
    xl[i] = __float2bfloat16(v - __bfloat162float(h));
}

// conv_w [o,c,k] -> cwt [k*DD+o][c] bf16 hi/lo
__global__ void transpose_cw_kernel(const float* __restrict__ cw,
                                    __nv_bfloat16* __restrict__ th,
                                    __nv_bfloat16* __restrict__ tl) {
    int idx = blockIdx.x * blockDim.x + threadIdx.x;
    if (idx >= DD * DD) return;
    int o = idx / DD, c = idx % DD;
    const float* src = cw + (long)idx * WW;
#pragma unroll
    for (int k = 0; k < WW; k++) {
        float v = src[k];
        __nv_bfloat16 h = __float2bfloat16(v);
        long off = ((long)k * DD + o) * DD + c;
        th[off] = h;
        tl[off] = __float2bfloat16(v - __bfloat162float(h));
    }
}

// shifted cumsum of G + relu -> bf16 hi/lo
__global__ void cumsum_relu_kernel(const float* __restrict__ G,
                                   __nv_bfloat16* __restrict__ ch,
                                   __nv_bfloat16* __restrict__ cl) {
    long id = (long)blockIdx.x * blockDim.x + threadIdx.x;
    if (id >= (long)BL * DD) return;
    int o  = (int)(id % DD);
    int bl = (int)(id / DD);
    int l  = bl % LL;
    int bt = bl - l;
    float s = 0.f;
#pragma unroll
    for (int k = 0; k < WW; k++) {
        int t = l + k;
        if (t < LL) s += G[((long)(bt + t) * WW + k) * DD + o];
        float v = fmaxf(s, 0.f);
        __nv_bfloat16 h = __float2bfloat16(v);
        long off = ((long)bl * WW + k) * DD + o;
        ch[off] = h;
        cl[off] = __float2bfloat16(v - __bfloat162float(h));
    }
}

// ---------------------------------------------------------------------------
// bf16 split GEMM via mma.sync:  C[m,n] = sum_k (Ah+Al)[m,k]*(Bh+Bl)[n,k]
// 3-term compensation: AhBh + AhBl + AlBh, fp32 accumulators.
// CTA tile 128x128, BK=32, 8 warps (2M x 4N), warp tile 64x32.
// smem: 4 tiles (Ah,Al,Bh,Bl) of 128 rows x 80B (32 bf16 padded), double-buffered.
#define ROWB 80
#define TILEB (128*ROWB)     // 10240
#define STAGEB (4*TILEB)     // 40960
#define SMEMB (2*STAGEB)     // 81920

template <int EPI>
__global__ __launch_bounds__(256)
void gemm_mma(const __nv_bfloat16* __restrict__ Ah, const __nv_bfloat16* __restrict__ Al, int lda,
              const __nv_bfloat16* __restrict__ Bh, const __nv_bfloat16* __restrict__ Bl, int ldb,
              float* __restrict__ C, __nv_bfloat16* __restrict__ Chi, __nv_bfloat16* __restrict__ Clo,
              int ldc, int K,
              const float* __restrict__ bias,
              const float* __restrict__ SA, const float* __restrict__ SB,
              const int* __restrict__ span32) {
    extern __shared__ char smem[];
    const uint32_t sbase = smem_u32(smem);
    const int tid = threadIdx.x, lane = tid & 31, wid = tid >> 5;
    const int wm = wid & 1, wn = wid >> 1;           // 2 x 4 warp grid
    const int m0 = blockIdx.y * 128, n0 = blockIdx.x * 128;
    const int NIT = K >> 5;

    const char* gA[4] = {
        (const char*)(Ah + (long)m0 * lda), (const char*)(Al + (long)m0 * lda),
        (const char*)(Bh + (long)n0 * ldb), (const char*)(Bl + (long)n0 * ldb) };
    const long ldbytes[4] = { (long)lda * 2, (long)lda * 2, (long)ldb * 2, (long)ldb * 2 };

    // each thread: per tile, 2 chunks of 16B (512 chunks / 256 threads)
    const int r0c = tid >> 2, kc0 = tid & 3;          // chunk tid
    const int r1c = (tid + 256) >> 2, kc1 = tid & 3;  // chunk tid+256

    auto issue_load = [&](int it) {
        const int k0b = (it << 5) * 2;                // k-offset in bytes
        const uint32_t st = sbase + (it & 1) * STAGEB;
#pragma unroll
        for (int t = 0; t < 4; t++) {
            cp16(st + t * TILEB + r0c * ROWB + kc0 * 16, gA[t] + (long)r0c * ldbytes[t] + k0b + kc0 * 16);
            cp16(st + t * TILEB + r1c * ROWB + kc1 * 16, gA[t] + (long)r1c * ldbytes[t] + k0b + kc1 * 16);
        }
    };

    float acc[4][4][4];
#pragma unroll
    for (int i = 0; i < 4; i++)
#pragma unroll
        for (int j = 0; j < 4; j++)
#pragma unroll
            for (int v = 0; v < 4; v++) acc[i][j][v] = 0.f;

    issue_load(0);
    CP_COMMIT();

    const uint32_t a_lane_off = (uint32_t)((wm * 64 + (lane & 15)) * ROWB + (lane >> 4) * 16);
    const uint32_t b_lane_off = (uint32_t)((wn * 32 + (lane & 15)) * ROWB + (lane >> 4) * 16);

    for (int it = 0; it < NIT; it++) {
        if (it + 1 < NIT) issue_load(it + 1);
        CP_COMMIT();
        CP_WAIT1();
        __syncthreads();

        const uint32_t st = sbase + (it & 1) * STAGEB;
#pragma unroll
        for (int ks = 0; ks < 2; ks++) {
            uint32_t ah[4][4], al[4][4];
#pragma unroll
            for (int mt = 0; mt < 4; mt++) {
                uint32_t addr = st + a_lane_off + mt * 16 * ROWB + ks * 32;
                LDSM4(ah[mt], addr);
                LDSM4(al[mt], addr + TILEB);
            }
            uint32_t bh[2][4], bl[2][4];
#pragma unroll
            for (int nb = 0; nb < 2; nb++) {
                uint32_t addr = st + 2 * TILEB + b_lane_off + nb * 16 * ROWB + ks * 32;
                LDSM4(bh[nb], addr);
                LDSM4(bl[nb], addr + TILEB);
            }
#pragma unroll
            for (int mt = 0; mt < 4; mt++)
#pragma unroll
                for (int nt = 0; nt < 4; nt++) {
                    const int nb = nt >> 1, sel = nt & 1;
                    MMA16816(acc[mt][nt], ah[mt], bh[nb][sel], bh[nb][sel + 2]);
                    MMA16816(acc[mt][nt], ah[mt], bl[nb][sel], bl[nb][sel + 2]);
                    MMA16816(acc[mt][nt], al[mt], bh[nb][sel], bh[nb][sel + 2]);
                }
        }
        __syncthreads();
    }

    // ---- epilogue ----
    const int qrow = lane >> 2, qcol = (lane & 3) * 2;
    const int is64 = (EPI == 2) ? g_is64 : 0;

#pragma unroll
    for (int mt = 0; mt < 4; mt++) {
        const int r0 = m0 + wm * 64 + mt * 16 + qrow;
        const int r1 = r0 + 8;

        int sw0 = 0, ew0 = 0, sw1 = 0, ew1 = 0, boff = 0;
        const float *sa0 = nullptr, *sb0 = nullptr, *sa1 = nullptr, *sb1 = nullptr;
        if (EPI == 2) {
            if (is64) {
                sw0 = span32[(long)r0 * 4]; ew0 = span32[(long)r0 * 4 + 2];
                sw1 = span32[(long)r1 * 4]; ew1 = span32[(long)r1 * 4 + 2];
            } else {
                sw0 = span32[(long)r0 * 2]; ew0 = span32[(long)r0 * 2 + 1];
                sw1 = span32[(long)r1 * 2]; ew1 = span32[(long)r1 * 2 + 1];
            }
            sw0 = min(max(sw0, 0), LL - 1); ew0 = min(max(ew0, 0), LL - 1);
            sw1 = min(max(sw1, 0), LL - 1); ew1 = min(max(ew1, 0), LL - 1);
            boff = (r0 / (LL * WW)) * LL;   // r0, r1 always in same batch (16 | LL*WW)
            sa0 = SA + (long)(boff + sw0) * DD; sb0 = SB + (long)(boff + ew0) * DD;
            sa1 = SA + (long)(boff + sw1) * DD; sb1 = SB + (long)(boff + ew1) * DD;
        }

#pragma unroll
        for (int nt = 0; nt < 4; nt++) {
            const int gc = n0 + wn * 32 + nt * 8 + qcol;
            const float* a = acc[mt][nt];
            if (EPI == 0) {
                *(float2*)(C + (long)r0 * ldc + gc) = make_float2(a[0], a[1]);
                *(float2*)(C + (long)r1 * ldc + gc) = make_float2(a[2], a[3]);
            } else if (EPI == 1) {
                float2 b = *(const float2*)(bias + gc);
                float v0 = fmaxf(a[0] + b.x, 0.f), v1 = fmaxf(a[1] + b.y, 0.f);
                float v2 = fmaxf(a[2] + b.x, 0.f), v3 = fmaxf(a[3] + b.y, 0.f);
                __nv_bfloat162 h01 = __floats2bfloat162_rn(v0, v1);
                __nv_bfloat162 h23 = __floats2bfloat162_rn(v2, v3);
                __nv_bfloat162 l01 = __floats2bfloat162_rn(v0 - __bfloat162float(h01.x),
                                                           v1 - __bfloat162float(h01.y));
                __nv_bfloat162 l23 = __floats2bfloat162_rn(v2 - __bfloat162float(h23.x),
                                                           v3 - __bfloat162float(h23.y));
                *(__nv_bfloat162*)(Chi + (long)r0 * ldc + gc) = h01;
                *(__nv_bfloat162*)(Chi + (long)r1 * ldc + gc) = h23;
                *(__nv_bfloat162*)(Clo + (long)r0 * ldc + gc) = l01;
                *(__nv_bfloat162*)(Clo + (long)r1 * ldc + gc) = l23;
            } else {
                float2 b  = *(const float2*)(bias + gc);
                float2 s0 = *(const float2*)(sa0 + gc), e0 = *(const float2*)(sb0 + gc);
                float2 s1 = *(const float2*)(sa1 + gc), e1 = *(const float2*)(sb1 + gc);
                float2 o0 = make_float2(fmaxf(a[0] + s0.x + e0.x + b.x, 0.f),
                                        fmaxf(a[1] + s0.y + e0.y + b.y, 0.f));
                float2 o1 = make_float2(fmaxf(a[2] + s1.x + e1.x + b.x, 0.f),
                                        fmaxf(a[3] + s1.y + e1.y + b.y, 0.f));
                *(float2*)(C + (long)r0 * ldc + gc) = o0;
                *(float2*)(C + (long)r1 * ldc + gc) = o1;
            }
        }
    }
}

// ---------------------------------------------------------------------------
extern "C" void kernel_launch(void* const* d_in, const int* in_sizes, int n_in,
                              void* d_out, int out_size) {
    const float* h      = (const float*)d_in[0];
    const int*   span32 = (const int*)d_in[1];
    const float* proj_w = (const float*)d_in[2];
    const float* proj_b = (const float*)d_in[3];
    const float* conv_w = (const float*)d_in[4];
    const float* out_w  = (const float*)d_in[5];
    const float* out_b  = (const float*)d_in[6];
    float*       out    = (float*)d_out;

    __nv_bfloat16 *hh, *hl, *pwh, *pwl, *owh, *owl, *cwth, *cwtl, *ph, *pl, *ch, *cl;
    float *G, *SA, *SB;
    cudaGetSymbolAddress((void**)&hh,   g_hh);   cudaGetSymbolAddress((void**)&hl,   g_hl);
    cudaGetSymbolAddress((void**)&pwh,  g_pwh);  cudaGetSymbolAddress((void**)&pwl,  g_pwl);
    cudaGetSymbolAddress((void**)&owh,  g_owh);  cudaGetSymbolAddress((void**)&owl,  g_owl);
    cudaGetSymbolAddress((void**)&cwth, g_cwth); cudaGetSymbolAddress((void**)&cwtl, g_cwtl);
    cudaGetSymbolAddress((void**)&ph,   g_ph);   cudaGetSymbolAddress((void**)&pl,   g_pl);
    cudaGetSymbolAddress((void**)&ch,   g_ch);   cudaGetSymbolAddress((void**)&cl,   g_cl);
    cudaGetSymbolAddress((void**)&G,    g_G);
    cudaGetSymbolAddress((void**)&SA,   g_SA);   cudaGetSymbolAddress((void**)&SB,   g_SB);

    cudaFuncSetAttribute((const void*)gemm_mma<0>, cudaFuncAttributeMaxDynamicSharedMemorySize, SMEMB);
    cudaFuncSetAttribute((const void*)gemm_mma<1>, cudaFuncAttributeMaxDynamicSharedMemorySize, SMEMB);
    cudaFuncSetAttribute((const void*)gemm_mma<2>, cudaFuncAttributeMaxDynamicSharedMemorySize, SMEMB);

    // 0. span_idx dtype detection (device-side, capturable)
    detect_idx_kernel<<<1, 256>>>(span32, BB * LL * WW * 2);

    // 1. fp32 -> bf16 hi/lo conversions
    split_kernel<<<((long)BL * DD + 255) / 256, 256>>>(h, hh, hl, (long)BL * DD);
    split_kernel<<<((long)TWOD * DD + 255) / 256, 256>>>(proj_w, pwh, pwl, (long)TWOD * DD);
    split_kernel<<<((long)DD * THREED + 255) / 256, 256>>>(out_w, owh, owl, (long)DD * THREED);
    transpose_cw_kernel<<<(DD * DD + 255) / 256, 256>>>(conv_w, cwth, cwtl);

    // 2. prelu = relu(h @ proj_w^T + proj_b) -> bf16 hi/lo   [BL, 2D]
    gemm_mma<1><<<dim3(TWOD / 128, BL / 128), 256, SMEMB>>>(
        hh, hl, DD, pwh, pwl, DD, nullptr, ph, pl, TWOD, DD, proj_b, nullptr, nullptr, nullptr);

    // 3. G = h @ cwt^T  (fp32)                               [BL, W*D]
    gemm_mma<0><<<dim3(WD / 128, BL / 128), 256, SMEMB>>>(
        hh, hl, DD, cwth, cwtl, DD, G, nullptr, nullptr, WD, DD, nullptr, nullptr, nullptr, nullptr);

    // 4. SA = prelu[:, :D] @ out_w[:, :D]^T                  [BL, D]
    gemm_mma<0><<<dim3(DD / 128, BL / 128), 256, SMEMB>>>(
        ph, pl, TWOD, owh, owl, THREED, SA, nullptr, nullptr, DD, DD,
        nullptr, nullptr, nullptr, nullptr);

    // 5. SB = prelu[:, D:] @ out_w[:, D:2D]^T                [BL, D]
    gemm_mma<0><<<dim3(DD / 128, BL / 128), 256, SMEMB>>>(
        ph + DD, pl + DD, TWOD, owh + DD, owl + DD, THREED, SB, nullptr, nullptr, DD, DD,
        nullptr, nullptr, nullptr, nullptr);

    // 6. convrelu = relu(shifted cumsum of G) -> bf16 hi/lo  [M_out, D]
    cumsum_relu_kernel<<<((long)BL * DD + 255) / 256, 256>>>(G, ch, cl);

    // 7. out = relu(conv @ out_w[:,2D:]^T + gather(SA) + gather(SB) + out_b)
    gemm_mma<2><<<dim3(DD / 128, MOUT / 128), 256, SMEMB>>>(
        ch, cl, DD, owh + TWOD, owl + TWOD, THREED, out, nullptr, nullptr, DD, DD,
        out_b, SA, SB, span32);
}

// round 9
// speedup vs baseline: 1.3827x; 1.3821x over previous
#include <cuda_runtime.h>
#include <cuda_fp16.h>
#include <cstdint>

#define BB 4
#define LL 512
#define DD 768
#define WW 12
#define TWOD 1536
#define THREED 2304
#define BL 2048
#define MOUT 24576
#define WD 9216

// ---- scratch (device globals; no allocation allowed) ----
__device__ __align__(16) __half g_hh[(long)BL*DD];                          // h fp16
__device__ __align__(16) __half g_pwh[(long)TWOD*DD],   g_pwl[(long)TWOD*DD];
__device__ __align__(16) __half g_owh[(long)DD*THREED], g_owl[(long)DD*THREED];
__device__ __align__(16) __half g_cwth[(long)WD*DD],    g_cwtl[(long)WD*DD];
__device__ __align__(16) __half g_ph[(long)BL*TWOD];                        // relu(proj) fp16
__device__ __align__(16) float  g_G[(long)BL*WD];
__device__ __align__(16) __half g_ch[(long)MOUT*DD];                        // relu(cumsum) fp16
__device__ __align__(16) float  g_SA[(long)BL*DD],      g_SB[(long)BL*DD];
__device__ int g_is64;

// ---- PTX helpers (baseline ISA only; valid on compute_103) ----
__device__ __forceinline__ uint32_t smem_u32(const void* p) {
    uint32_t a;
    asm("{ .reg .u64 t; cvta.to.shared.u64 t, %1; cvt.u32.u64 %0, t; }" : "=r"(a) : "l"(p));
    return a;
}
__device__ __forceinline__ void cp16(uint32_t dst, const void* src) {
    asm volatile("cp.async.cg.shared.global [%0], [%1], 16;" :: "r"(dst), "l"(src));
}
#define CP_COMMIT() asm volatile("cp.async.commit_group;" ::: "memory")
#define CP_WAIT1()  asm volatile("cp.async.wait_group 1;" ::: "memory")

#define LDSM4(r, addr) \
    asm volatile("ldmatrix.sync.aligned.m8n8.x4.shared.b16 {%0,%1,%2,%3}, [%4];" \
        : "=r"((r)[0]), "=r"((r)[1]), "=r"((r)[2]), "=r"((r)[3]) : "r"(addr))

#define MMA16816(acc, a, b0, b1) \
    asm volatile("mma.sync.aligned.m16n8k16.row.col.f32.f16.f16.f32 " \
        "{%0,%1,%2,%3}, {%4,%5,%6,%7}, {%8,%9}, {%0,%1,%2,%3};" \
        : "+f"((acc)[0]), "+f"((acc)[1]), "+f"((acc)[2]), "+f"((acc)[3]) \
        : "r"((a)[0]), "r"((a)[1]), "r"((a)[2]), "r"((a)[3]), "r"(b0), "r"(b1))

// ---------------------------------------------------------------------------
__global__ void detect_idx_kernel(const int* __restrict__ p, int nwords) {
    __shared__ int any;
    if (threadIdx.x == 0) any = 0;
    __syncthreads();
    int found = 0;
    for (int i = threadIdx.x; 2 * i + 1 < nwords; i += blockDim.x)
        found |= (p[2 * i + 1] != 0);
    if (found) atomicOr(&any, 1);
    __syncthreads();
    if (threadIdx.x == 0) g_is64 = (any == 0) ? 1 : 0;
}

// fp32 -> fp16 (plain)
__global__ void tofp16_kernel(const float* __restrict__ x, __half* __restrict__ y, long n) {
    long i = (long)blockIdx.x * blockDim.x + threadIdx.x;
    if (i >= n) return;
    y[i] = __float2half_rn(x[i]);
}

// fp32 -> (hi, lo) fp16 split (weights)
__global__ void split_kernel(const float* __restrict__ x,
                             __half* __restrict__ xh, __half* __restrict__ xl, long n) {
    long i = (long)blockIdx.x * blockDim.x + threadIdx.x;
    if (i >= n) return;
    float v = x[i];
    __half h = __float2half_rn(v);
    xh[i] = h;
    xl[i] = __float2half_rn(v - __half2float(h));
}

// conv_w [o,c,k] -> cwt [k*DD+o][c] fp16 hi/lo
__global__ void transpose_cw_kernel(const float* __restrict__ cw,
                                    __half* __restrict__ th, __half* __restrict__ tl) {
    int idx = blockIdx.x * blockDim.x + threadIdx.x;
    if (idx >= DD * DD) return;
    int o = idx / DD, c = idx % DD;
    const float* src = cw + (long)idx * WW;
#pragma unroll
    for (int k = 0; k < WW; k++) {
        float v = src[k];
        __half h = __float2half_rn(v);
        long off = ((long)k * DD + o) * DD + c;
        th[off] = h;
        tl[off] = __float2half_rn(v - __half2float(h));
    }
}

// shifted cumsum of G (fp32) + relu -> fp16
__global__ void cumsum_relu_kernel(const float* __restrict__ G, __half* __restrict__ ch) {
    long id = (long)blockIdx.x * blockDim.x + threadIdx.x;
    if (id >= (long)BL * DD) return;
    int o  = (int)(id % DD);
    int bl = (int)(id / DD);
    int l  = bl % LL;
    int bt = bl - l;
    float s = 0.f;
#pragma unroll
    for (int k = 0; k < WW; k++) {
        int t = l + k;
        if (t < LL) s += G[((long)(bt + t) * WW + k) * DD + o];
        ch[((long)bl * WW + k) * DD + o] = __float2half_rn(fmaxf(s, 0.f));
    }
}

// ---------------------------------------------------------------------------
// fp16 2-term GEMM via mma.sync:  C[m,n] = sum_k A[m,k]*(Bh+Bl)[n,k]   (fp32 acc)
// A plain fp16 (activations); B split hi/lo fp16 (weights, residual exact).
// CTA tile 128x128, BK=32, 8 warps (2M x 4N), warp tile 64x32.
// smem per stage: A(10K) Bh(10K) Bl(10K); double-buffered = 60KB -> 2 CTAs/SM.
#define ROWB 80
#define TILEB (128*ROWB)     // 10240
#define STAGEB (3*TILEB)     // 30720
#define SMEMB (2*STAGEB)     // 61440

template <int EPI>
__global__ __launch_bounds__(256, 2)
void gemm_mma(const __half* __restrict__ A, int lda,
              const __half* __restrict__ Bh, const __half* __restrict__ Bl, int ldb,
              float* __restrict__ C, __half* __restrict__ Cf16,
              int ldc, int K,
              const float* __restrict__ bias,
              const float* __restrict__ SA, const float* __restrict__ SB,
              const int* __restrict__ span32) {
    extern __shared__ char smem[];
    const uint32_t sbase = smem_u32(smem);
    const int tid = threadIdx.x, lane = tid & 31, wid = tid >> 5;
    const int wm = wid & 1, wn = wid >> 1;           // 2 x 4 warp grid
    const int m0 = blockIdx.y * 128, n0 = blockIdx.x * 128;
    const int NIT = K >> 5;

    const char* gT[3] = {
        (const char*)(A  + (long)m0 * lda),
        (const char*)(Bh + (long)n0 * ldb),
        (const char*)(Bl + (long)n0 * ldb) };
    const long ldby[3] = { (long)lda * 2, (long)ldb * 2, (long)ldb * 2 };

    const int r0c = tid >> 2, kc0 = tid & 3;          // chunk tid
    const int r1c = (tid + 256) >> 2, kc1 = tid & 3;  // chunk tid+256

    auto issue_load = [&](int it) {
        const int k0b = it << 6;                      // it*32 cols * 2B
        const uint32_t st = sbase + (it & 1) * STAGEB;
#pragma unroll
        for (int t = 0; t < 3; t++) {
            cp16(st + t * TILEB + r0c * ROWB + kc0 * 16, gT[t] + (long)r0c * ldby[t] + k0b + kc0 * 16);
            cp16(st + t * TILEB + r1c * ROWB + kc1 * 16, gT[t] + (long)r1c * ldby[t] + k0b + kc1 * 16);
        }
    };

    float acc[4][4][4];
#pragma unroll
    for (int i = 0; i < 4; i++)
#pragma unroll
        for (int j = 0; j < 4; j++)
#pragma unroll
            for (int v = 0; v < 4; v++) acc[i][j][v] = 0.f;

    issue_load(0);
    CP_COMMIT();

    const uint32_t a_lane_off = (uint32_t)((wm * 64 + (lane & 15)) * ROWB + (lane >> 4) * 16);
    const uint32_t b_lane_off = (uint32_t)((wn * 32 + (lane & 15)) * ROWB + (lane >> 4) * 16);

    for (int it = 0; it < NIT; it++) {
        if (it + 1 < NIT) issue_load(it + 1);
        CP_COMMIT();
        CP_WAIT1();
        __syncthreads();

        const uint32_t st = sbase + (it & 1) * STAGEB;
#pragma unroll
        for (int ks = 0; ks < 2; ks++) {
            uint32_t a[4][4];
#pragma unroll
            for (int mt = 0; mt < 4; mt++)
                LDSM4(a[mt], st + a_lane_off + mt * 16 * ROWB + ks * 32);
            uint32_t bh[2][4], bl[2][4];
#pragma unroll
            for (int nb = 0; nb < 2; nb++) {
                uint32_t addr = st + TILEB + b_lane_off + nb * 16 * ROWB + ks * 32;
                LDSM4(bh[nb], addr);
                LDSM4(bl[nb], addr + TILEB);
            }
#pragma unroll
            for (int mt = 0; mt < 4; mt++)
#pragma unroll
                for (int nt = 0; nt < 4; nt++) {
                    const int nb = nt >> 1, sel = nt & 1;
                    MMA16816(acc[mt][nt], a[mt], bh[nb][sel], bh[nb][sel + 2]);
                    MMA16816(acc[mt][nt], a[mt], bl[nb][sel], bl[nb][sel + 2]);
                }
        }
        __syncthreads();
    }

    // ---- epilogue ----
    const int qrow = lane >> 2, qcol = (lane & 3) * 2;
    const int is64 = (EPI == 2) ? g_is64 : 0;

#pragma unroll
    for (int mt = 0; mt < 4; mt++) {
        const int r0 = m0 + wm * 64 + mt * 16 + qrow;
        const int r1 = r0 + 8;

        const float *sa0 = nullptr, *sb0 = nullptr, *sa1 = nullptr, *sb1 = nullptr;
        if (EPI == 2) {
            int sw0, ew0, sw1, ew1;
            if (is64) {
                sw0 = span32[(long)r0 * 4]; ew0 = span32[(long)r0 * 4 + 2];
                sw1 = span32[(long)r1 * 4]; ew1 = span32[(long)r1 * 4 + 2];
            } else {
                sw0 = span32[(long)r0 * 2]; ew0 = span32[(long)r0 * 2 + 1];
                sw1 = span32[(long)r1 * 2]; ew1 = span32[(long)r1 * 2 + 1];
            }
            sw0 = min(max(sw0, 0), LL - 1); ew0 = min(max(ew0, 0), LL - 1);
            sw1 = min(max(sw1, 0), LL - 1); ew1 = min(max(ew1, 0), LL - 1);
            int boff = (r0 / (LL * WW)) * LL;   // r0, r1 always in same batch (16 | LL*WW)
            sa0 = SA + (long)(boff + sw0) * DD; sb0 = SB + (long)(boff + ew0) * DD;
            sa1 = SA + (long)(boff + sw1) * DD; sb1 = SB + (long)(boff + ew1) * DD;
        }

#pragma unroll
        for (int nt = 0; nt < 4; nt++) {
            const int gc = n0 + wn * 32 + nt * 8 + qcol;
            const float* a = acc[mt][nt];
            if (EPI == 0) {
                *(float2*)(C + (long)r0 * ldc + gc) = make_float2(a[0], a[1]);
                *(float2*)(C + (long)r1 * ldc + gc) = make_float2(a[2], a[3]);
            } else if (EPI == 1) {
                float2 b = *(const float2*)(bias + gc);
                *(__half2*)(Cf16 + (long)r0 * ldc + gc) =
                    __floats2half2_rn(fmaxf(a[0] + b.x, 0.f), fmaxf(a[1] + b.y, 0.f));
                *(__half2*)(Cf16 + (long)r1 * ldc + gc) =
                    __floats2half2_rn(fmaxf(a[2] + b.x, 0.f), fmaxf(a[3] + b.y, 0.f));
            } else {
                float2 b  = *(const float2*)(bias + gc);
                float2 s0 = *(const float2*)(sa0 + gc), e0 = *(const float2*)(sb0 + gc);
                float2 s1 = *(const float2*)(sa1 + gc), e1 = *(const float2*)(sb1 + gc);
                float2 o0 = make_float2(fmaxf(a[0] + s0.x + e0.x + b.x, 0.f),
                                        fmaxf(a[1] + s0.y + e0.y + b.y, 0.f));
                float2 o1 = make_float2(fmaxf(a[2] + s1.x + e1.x + b.x, 0.f),
                                        fmaxf(a[3] + s1.y + e1.y + b.y, 0.f));
                *(float2*)(C + (long)r0 * ldc + gc) = o0;
                *(float2*)(C + (long)r1 * ldc + gc) = o1;
            }
        }
    }
}

// ---------------------------------------------------------------------------
extern "C" void kernel_launch(void* const* d_in, const int* in_sizes, int n_in,
                              void* d_out, int out_size) {
    const float* h      = (const float*)d_in[0];
    const int*   span32 = (const int*)d_in[1];
    const float* proj_w = (const float*)d_in[2];
    const float* proj_b = (const float*)d_in[3];
    const float* conv_w = (const float*)d_in[4];
    const float* out_w  = (const float*)d_in[5];
    const float* out_b  = (const float*)d_in[6];
    float*       out    = (float*)d_out;

    __half *hh, *pwh, *pwl, *owh, *owl, *cwth, *cwtl, *ph, *ch;
    float *G, *SA, *SB;
    cudaGetSymbolAddress((void**)&hh,   g_hh);
    cudaGetSymbolAddress((void**)&pwh,  g_pwh);  cudaGetSymbolAddress((void**)&pwl,  g_pwl);
    cudaGetSymbolAddress((void**)&owh,  g_owh);  cudaGetSymbolAddress((void**)&owl,  g_owl);
    cudaGetSymbolAddress((void**)&cwth, g_cwth); cudaGetSymbolAddress((void**)&cwtl, g_cwtl);
    cudaGetSymbolAddress((void**)&ph,   g_ph);
    cudaGetSymbolAddress((void**)&ch,   g_ch);
    cudaGetSymbolAddress((void**)&G,    g_G);
    cudaGetSymbolAddress((void**)&SA,   g_SA);   cudaGetSymbolAddress((void**)&SB,   g_SB);

    cudaFuncSetAttribute((const void*)gemm_mma<0>, cudaFuncAttributeMaxDynamicSharedMemorySize, SMEMB);
    cudaFuncSetAttribute((const void*)gemm_mma<1>, cudaFuncAttributeMaxDynamicSharedMemorySize, SMEMB);
    cudaFuncSetAttribute((const void*)gemm_mma<2>, cudaFuncAttributeMaxDynamicSharedMemorySize, SMEMB);

    // 0. span_idx dtype detection (device-side, capturable)
    detect_idx_kernel<<<1, 256>>>(span32, BB * LL * WW * 2);

    // 1. conversions: activations plain fp16; weights split fp16 hi/lo
    tofp16_kernel<<<((long)BL * DD + 255) / 256, 256>>>(h, hh, (long)BL * DD);
    split_kernel<<<((long)TWOD * DD + 255) / 256, 256>>>(proj_w, pwh, pwl, (long)TWOD * DD);
    split_kernel<<<((long)DD * THREED + 255) / 256, 256>>>(out_w, owh, owl, (long)DD * THREED);
    transpose_cw_kernel<<<(DD * DD + 255) / 256, 256>>>(conv_w, cwth, cwtl);

    // 2. prelu = relu(h @ proj_w^T + proj_b) -> fp16          [BL, 2D]
    gemm_mma<1><<<dim3(TWOD / 128, BL / 128), 256, SMEMB>>>(
        hh, DD, pwh, pwl, DD, nullptr, ph, TWOD, DD, proj_b, nullptr, nullptr, nullptr);

    // 3. G = h @ cwt^T  (fp32)                                [BL, W*D]
    gemm_mma<0><<<dim3(WD / 128, BL / 128), 256, SMEMB>>>(
        hh, DD, cwth, cwtl, DD, G, nullptr, WD, DD, nullptr, nullptr, nullptr, nullptr);

    // 4. SA = prelu[:, :D] @ out_w[:, :D]^T                   [BL, D]
    gemm_mma<0><<<dim3(DD / 128, BL / 128), 256, SMEMB>>>(
        ph, TWOD, owh, owl, THREED, SA, nullptr, DD, DD, nullptr, nullptr, nullptr, nullptr);

    // 5. SB = prelu[:, D:] @ out_w[:, D:2D]^T                 [BL, D]
    gemm_mma<0><<<dim3(DD / 128, BL / 128), 256, SMEMB>>>(
        ph + DD, TWOD, owh + DD, owl + DD, THREED, SB, nullptr, DD, DD,
        nullptr, nullptr, nullptr, nullptr);

    // 6. convrelu = relu(shifted cumsum of G) -> fp16         [M_out, D]
    cumsum_relu_kernel<<<((long)BL * DD + 255) / 256, 256>>>(G, ch);

    // 7. out = relu(conv @ out_w[:,2D:]^T + gather(SA) + gather(SB) + out_b)
    gemm_mma<2><<<dim3(DD / 128, MOUT / 128), 256, SMEMB>>>(
        ch, DD, owh + TWOD, owl + TWOD, THREED, out, nullptr, DD, DD,
        out_b, SA, SB, span32);
}

// round 10
// speedup vs baseline: 2.2213x; 1.6065x over previous
#include <cuda_runtime.h>
#include <cuda_fp16.h>
#include <cstdint>

#define BB 4
#define LL 512
#define DD 768
#define WW 12
#define TWOD 1536
#define THREED 2304
#define BL 2048
#define MOUT 24576
#define WD 9216

// ---- scratch (device globals; no allocation allowed) ----
__device__ __align__(16) __half g_hh[(long)BL*DD];                // h fp16
__device__ __align__(16) __half g_pwh[(long)TWOD*DD];             // proj_w fp16
__device__ __align__(16) __half g_owh[(long)DD*THREED];           // out_w fp16
__device__ __align__(16) __half g_cwth[(long)WD*DD];              // conv_w transposed fp16
__device__ __align__(16) __half g_ph[(long)BL*TWOD];              // relu(proj) fp16
__device__ __align__(16) float  g_G[(long)BL*WD];
__device__ __align__(16) __half g_ch[(long)MOUT*DD];              // relu(cumsum) fp16
__device__ __align__(16) float  g_SA[(long)BL*DD], g_SB[(long)BL*DD];
__device__ int g_is64;

// ---- PTX helpers (baseline ISA only; valid on compute_103) ----
__device__ __forceinline__ uint32_t smem_u32(const void* p) {
    uint32_t a;
    asm("{ .reg .u64 t; cvta.to.shared.u64 t, %1; cvt.u32.u64 %0, t; }" : "=r"(a) : "l"(p));
    return a;
}
__device__ __forceinline__ void cp16(uint32_t dst, const void* src) {
    asm volatile("cp.async.cg.shared.global [%0], [%1], 16;" :: "r"(dst), "l"(src));
}
#define CP_COMMIT() asm volatile("cp.async.commit_group;" ::: "memory")
#define CP_WAIT1()  asm volatile("cp.async.wait_group 1;" ::: "memory")

#define LDSM4(r, addr) \
    asm volatile("ldmatrix.sync.aligned.m8n8.x4.shared.b16 {%0,%1,%2,%3}, [%4];" \
        : "=r"((r)[0]), "=r"((r)[1]), "=r"((r)[2]), "=r"((r)[3]) : "r"(addr))

#define MMA16816(acc, a, b0, b1) \
    asm volatile("mma.sync.aligned.m16n8k16.row.col.f32.f16.f16.f32 " \
        "{%0,%1,%2,%3}, {%4,%5,%6,%7}, {%8,%9}, {%0,%1,%2,%3};" \
        : "+f"((acc)[0]), "+f"((acc)[1]), "+f"((acc)[2]), "+f"((acc)[3]) \
        : "r"((a)[0]), "r"((a)[1]), "r"((a)[2]), "r"((a)[3]), "r"(b0), "r"(b1))

// ---------------------------------------------------------------------------
__global__ void detect_idx_kernel(const int* __restrict__ p, int nwords) {
    __shared__ int any;
    if (threadIdx.x == 0) any = 0;
    __syncthreads();
    int found = 0;
    for (int i = threadIdx.x; 2 * i + 1 < nwords; i += blockDim.x)
        found |= (p[2 * i + 1] != 0);
    if (found) atomicOr(&any, 1);
    __syncthreads();
    if (threadIdx.x == 0) g_is64 = (any == 0) ? 1 : 0;
}

// fp32 -> fp16
__global__ void tofp16_kernel(const float* __restrict__ x, __half* __restrict__ y, long n) {
    long i = (long)blockIdx.x * blockDim.x + threadIdx.x;
    if (i >= n) return;
    y[i] = __float2half_rn(x[i]);
}

// conv_w [o,c,k] -> cwt [k*DD+o][c] fp16
__global__ void transpose_cw_kernel(const float* __restrict__ cw, __half* __restrict__ th) {
    int idx = blockIdx.x * blockDim.x + threadIdx.x;
    if (idx >= DD * DD) return;
    int o = idx / DD, c = idx % DD;
    const float* src = cw + (long)idx * WW;
#pragma unroll
    for (int k = 0; k < WW; k++)
        th[((long)k * DD + o) * DD + c] = __float2half_rn(src[k]);
}

// shifted cumsum of G (fp32) + relu -> fp16
__global__ void cumsum_relu_kernel(const float* __restrict__ G, __half* __restrict__ ch) {
    long id = (long)blockIdx.x * blockDim.x + threadIdx.x;
    if (id >= (long)BL * DD) return;
    int o  = (int)(id % DD);
    int bl = (int)(id / DD);
    int l  = bl % LL;
    int bt = bl - l;
    float s = 0.f;
#pragma unroll
    for (int k = 0; k < WW; k++) {
        int t = l + k;
        if (t < LL) s += G[((long)(bt + t) * WW + k) * DD + o];
        ch[((long)bl * WW + k) * DD + o] = __float2half_rn(fmaxf(s, 0.f));
    }
}

// ---------------------------------------------------------------------------
// fp16 GEMM via mma.sync:  C[m,n] = sum_k A[m,k]*B[n,k]   (fp32 acc)
// CTA tile 128x128, BK=32, 8 warps (2M x 4N), warp tile 64x32.
// 3-stage cp.async pipeline; one __syncthreads per K-iter.
// smem per stage: A(10K) B(10K); 3 stages = 60KB -> 2 CTAs/SM.
#define ROWB 80
#define TILEB (128*ROWB)     // 10240
#define STAGEB (2*TILEB)     // 20480
#define NSTG 3
#define SMEMB (NSTG*STAGEB)  // 61440

template <int EPI>
__global__ __launch_bounds__(256, 2)
void gemm_mma(const __half* __restrict__ A, int lda,
              const __half* __restrict__ B, int ldb,
              float* __restrict__ C, __half* __restrict__ Cf16,
              int ldc, int K,
              const float* __restrict__ bias,
              const float* __restrict__ SA, const float* __restrict__ SB,
              const int* __restrict__ span32) {
    extern __shared__ char smem[];
    const uint32_t sbase = smem_u32(smem);
    const int tid = threadIdx.x, lane = tid & 31, wid = tid >> 5;
    const int wm = wid & 1, wn = wid >> 1;           // 2 x 4 warp grid
    const int m0 = blockIdx.y * 128, n0 = blockIdx.x * 128;
    const int NIT = K >> 5;

    const char* gT[2] = { (const char*)(A + (long)m0 * lda),
                          (const char*)(B + (long)n0 * ldb) };
    const long ldby[2] = { (long)lda * 2, (long)ldb * 2 };

    const int r0c = tid >> 2, kc0 = tid & 3;          // chunk tid
    const int r1c = (tid + 256) >> 2, kc1 = tid & 3;  // chunk tid+256

    auto issue_load = [&](int it) {
        const int k0b = it << 6;                      // it*32 cols * 2B
        const uint32_t st = sbase + (it % NSTG) * STAGEB;
#pragma unroll
        for (int t = 0; t < 2; t++) {
            cp16(st + t * TILEB + r0c * ROWB + kc0 * 16, gT[t] + (long)r0c * ldby[t] + k0b + kc0 * 16);
            cp16(st + t * TILEB + r1c * ROWB + kc1 * 16, gT[t] + (long)r1c * ldby[t] + k0b + kc1 * 16);
        }
    };

    float acc[4][4][4];
#pragma unroll
    for (int i = 0; i < 4; i++)
#pragma unroll
        for (int j = 0; j < 4; j++)
#pragma unroll
            for (int v = 0; v < 4; v++) acc[i][j][v] = 0.f;

    issue_load(0); CP_COMMIT();
    issue_load(1); CP_COMMIT();

    const uint32_t a_lane_off = (uint32_t)((wm * 64 + (lane & 15)) * ROWB + (lane >> 4) * 16);
    const uint32_t b_lane_off = (uint32_t)((wn * 32 + (lane & 15)) * ROWB + (lane >> 4) * 16);

    for (int it = 0; it < NIT; it++) {
        CP_WAIT1();
        __syncthreads();

        const uint32_t st = sbase + (it % NSTG) * STAGEB;
#pragma unroll
        for (int ks = 0; ks < 2; ks++) {
            uint32_t a[4][4];
#pragma unroll
            for (int mt = 0; mt < 4; mt++)
                LDSM4(a[mt], st + a_lane_off + mt * 16 * ROWB + ks * 32);
            uint32_t b[2][4];
#pragma unroll
            for (int nb = 0; nb < 2; nb++)
                LDSM4(b[nb], st + TILEB + b_lane_off + nb * 16 * ROWB + ks * 32);
#pragma unroll
            for (int mt = 0; mt < 4; mt++)
#pragma unroll
                for (int nt = 0; nt < 4; nt++) {
                    const int nb = nt >> 1, sel = nt & 1;
                    MMA16816(acc[mt][nt], a[mt], b[nb][sel], b[nb][sel + 2]);
                }
        }
        if (it + 2 < NIT) issue_load(it + 2);
        CP_COMMIT();
    }

    // ---- epilogue ----
    const int qrow = lane >> 2, qcol = (lane & 3) * 2;
    const int is64 = (EPI == 2) ? g_is64 : 0;

#pragma unroll
    for (int mt = 0; mt < 4; mt++) {
        const int r0 = m0 + wm * 64 + mt * 16 + qrow;
        const int r1 = r0 + 8;

        const float *sa0 = nullptr, *sb0 = nullptr, *sa1 = nullptr, *sb1 = nullptr;
        if (EPI == 2) {
            int sw0, ew0, sw1, ew1;
            if (is64) {
                sw0 = span32[(long)r0 * 4]; ew0 = span32[(long)r0 * 4 + 2];
                sw1 = span32[(long)r1 * 4]; ew1 = span32[(long)r1 * 4 + 2];
            } else {
                sw0 = span32[(long)r0 * 2]; ew0 = span32[(long)r0 * 2 + 1];
                sw1 = span32[(long)r1 * 2]; ew1 = span32[(long)r1 * 2 + 1];
            }
            sw0 = min(max(sw0, 0), LL - 1); ew0 = min(max(ew0, 0), LL - 1);
            sw1 = min(max(sw1, 0), LL - 1); ew1 = min(max(ew1, 0), LL - 1);
            int boff = (r0 / (LL * WW)) * LL;   // r0, r1 always in same batch (16 | LL*WW)
            sa0 = SA + (long)(boff + sw0) * DD; sb0 = SB + (long)(boff + ew0) * DD;
            sa1 = SA + (long)(boff + sw1) * DD; sb1 = SB + (long)(boff + ew1) * DD;
        }

#pragma unroll
        for (int nt = 0; nt < 4; nt++) {
            const int gc = n0 + wn * 32 + nt * 8 + qcol;
            const float* a = acc[mt][nt];
            if (EPI == 0) {
                *(float2*)(C + (long)r0 * ldc + gc) = make_float2(a[0], a[1]);
                *(float2*)(C + (long)r1 * ldc + gc) = make_float2(a[2], a[3]);
            } else if (EPI == 1) {
                float2 b = *(const float2*)(bias + gc);
                *(__half2*)(Cf16 + (long)r0 * ldc + gc) =
                    __floats2half2_rn(fmaxf(a[0] + b.x, 0.f), fmaxf(a[1] + b.y, 0.f));
                *(__half2*)(Cf16 + (long)r1 * ldc + gc) =
                    __floats2half2_rn(fmaxf(a[2] + b.x, 0.f), fmaxf(a[3] + b.y, 0.f));
            } else {
                float2 b  = *(const float2*)(bias + gc);
                float2 s0 = *(const float2*)(sa0 + gc), e0 = *(const float2*)(sb0 + gc);
                float2 s1 = *(const float2*)(sa1 + gc), e1 = *(const float2*)(sb1 + gc);
                float2 o0 = make_float2(fmaxf(a[0] + s0.x + e0.x + b.x, 0.f),
                                        fmaxf(a[1] + s0.y + e0.y + b.y, 0.f));
                float2 o1 = make_float2(fmaxf(a[2] + s1.x + e1.x + b.x, 0.f),
                                        fmaxf(a[3] + s1.y + e1.y + b.y, 0.f));
                *(float2*)(C + (long)r0 * ldc + gc) = o0;
                *(float2*)(C + (long)r1 * ldc + gc) = o1;
            }
        }
    }
}

// ---------------------------------------------------------------------------
extern "C" void kernel_launch(void* const* d_in, const int* in_sizes, int n_in,
                              void* d_out, int out_size) {
    const float* h      = (const float*)d_in[0];
    const int*   span32 = (const int*)d_in[1];
    const float* proj_w = (const float*)d_in[2];
    const float* proj_b = (const float*)d_in[3];
    const float* conv_w = (const float*)d_in[4];
    const float* out_w  = (const float*)d_in[5];
    const float* out_b  = (const float*)d_in[6];
    float*       out    = (float*)d_out;

    __half *hh, *pwh, *owh, *cwth, *ph, *ch;
    float *G, *SA, *SB;
    cudaGetSymbolAddress((void**)&hh,   g_hh);
    cudaGetSymbolAddress((void**)&pwh,  g_pwh);
    cudaGetSymbolAddress((void**)&owh,  g_owh);
    cudaGetSymbolAddress((void**)&cwth, g_cwth);
    cudaGetSymbolAddress((void**)&ph,   g_ph);
    cudaGetSymbolAddress((void**)&ch,   g_ch);
    cudaGetSymbolAddress((void**)&G,    g_G);
    cudaGetSymbolAddress((void**)&SA,   g_SA);
    cudaGetSymbolAddress((void**)&SB,   g_SB);

    cudaFuncSetAttribute((const void*)gemm_mma<0>, cudaFuncAttributeMaxDynamicSharedMemorySize, SMEMB);
    cudaFuncSetAttribute((const void*)gemm_mma<1>, cudaFuncAttributeMaxDynamicSharedMemorySize, SMEMB);
    cudaFuncSetAttribute((const void*)gemm_mma<2>, cudaFuncAttributeMaxDynamicSharedMemorySize, SMEMB);

    // 0. span_idx dtype detection (device-side, capturable)
    detect_idx_kernel<<<1, 256>>>(span32, BB * LL * WW * 2);

    // 1. conversions: all operands plain fp16
    tofp16_kernel<<<((long)BL * DD + 255) / 256, 256>>>(h, hh, (long)BL * DD);
    tofp16_kernel<<<((long)TWOD * DD + 255) / 256, 256>>>(proj_w, pwh, (long)TWOD * DD);
    tofp16_kernel<<<((long)DD * THREED + 255) / 256, 256>>>(out_w, owh, (long)DD * THREED);
    transpose_cw_kernel<<<(DD * DD + 255) / 256, 256>>>(conv_w, cwth);

    // 2. prelu = relu(h @ proj_w^T + proj_b) -> fp16          [BL, 2D]
    gemm_mma<1><<<dim3(TWOD / 128, BL / 128), 256, SMEMB>>>(
        hh, DD, pwh, DD, nullptr, ph, TWOD, DD, proj_b, nullptr, nullptr, nullptr);

    // 3. G = h @ cwt^T  (fp32)                                [BL, W*D]
    gemm_mma<0><<<dim3(WD / 128, BL / 128), 256, SMEMB>>>(
        hh, DD, cwth, DD, G, nullptr, WD, DD, nullptr, nullptr, nullptr, nullptr);

    // 4. SA = prelu[:, :D] @ out_w[:, :D]^T                   [BL, D]
    gemm_mma<0><<<dim3(DD / 128, BL / 128), 256, SMEMB>>>(
        ph, TWOD, owh, THREED, SA, nullptr, DD, DD, nullptr, nullptr, nullptr, nullptr);

    // 5. SB = prelu[:, D:] @ out_w[:, D:2D]^T                 [BL, D]
    gemm_mma<0><<<dim3(DD / 128, BL / 128), 256, SMEMB>>>(
        ph + DD, TWOD, owh + DD, THREED, SB, nullptr, DD, DD,
        nullptr, nullptr, nullptr, nullptr);

    // 6. convrelu = relu(shifted cumsum of G) -> fp16         [M_out, D]
    cumsum_relu_kernel<<<((long)BL * DD + 255) / 256, 256>>>(G, ch);

    // 7. out = relu(conv @ out_w[:,2D:]^T + gather(SA) + gather(SB) + out_b)
    gemm_mma<2><<<dim3(DD / 128, MOUT / 128), 256, SMEMB>>>(
        ch, DD, owh + TWOD, THREED, out, nullptr, DD, DD,
        out_b, SA, SB, span32);
}

// round 11
// speedup vs baseline: 2.2277x; 1.0029x over previous
#include <cuda_runtime.h>
#include <cuda_fp16.h>
#include <cstdint>

#define BB 4
#define LL 512
#define DD 768
#define WW 12
#define TWOD 1536
#define THREED 2304
#define BL 2048
#define MOUT 24576
#define WD 9216

// ---- scratch (device globals; no allocation allowed) ----
__device__ __align__(16) __half g_hh[(long)BL*DD];                // h fp16
__device__ __align__(16) __half g_pwh[(long)TWOD*DD];             // proj_w fp16
__device__ __align__(16) __half g_owh[(long)DD*THREED];           // out_w fp16
__device__ __align__(16) __half g_cwth[(long)WD*DD];              // conv_w transposed fp16
__device__ __align__(16) __half g_ph[(long)BL*TWOD];              // relu(proj) fp16
__device__ __align__(16) __half g_G[(long)BL*WD];                 // conv contributions fp16
__device__ __align__(16) __half g_ch[(long)MOUT*DD];              // relu(cumsum) fp16
__device__ __align__(16) float  g_SA[(long)BL*DD], g_SB[(long)BL*DD];
__device__ int g_is64;

// ---- PTX helpers (baseline ISA only; valid on compute_103) ----
__device__ __forceinline__ uint32_t smem_u32(const void* p) {
    uint32_t a;
    asm("{ .reg .u64 t; cvta.to.shared.u64 t, %1; cvt.u32.u64 %0, t; }" : "=r"(a) : "l"(p));
    return a;
}
__device__ __forceinline__ void cp16(uint32_t dst, const void* src) {
    asm volatile("cp.async.cg.shared.global [%0], [%1], 16;" :: "r"(dst), "l"(src));
}
#define CP_COMMIT() asm volatile("cp.async.commit_group;" ::: "memory")
#define CP_WAIT1()  asm volatile("cp.async.wait_group 1;" ::: "memory")

#define LDSM4(r, addr) \
    asm volatile("ldmatrix.sync.aligned.m8n8.x4.shared.b16 {%0,%1,%2,%3}, [%4];" \
        : "=r"((r)[0]), "=r"((r)[1]), "=r"((r)[2]), "=r"((r)[3]) : "r"(addr))

#define MMA16816(acc, a, b0, b1) \
    asm volatile("mma.sync.aligned.m16n8k16.row.col.f32.f16.f16.f32 " \
        "{%0,%1,%2,%3}, {%4,%5,%6,%7}, {%8,%9}, {%0,%1,%2,%3};" \
        : "+f"((acc)[0]), "+f"((acc)[1]), "+f"((acc)[2]), "+f"((acc)[3]) \
        : "r"((a)[0]), "r"((a)[1]), "r"((a)[2]), "r"((a)[3]), "r"(b0), "r"(b1))

// ---------------------------------------------------------------------------
__global__ void detect_idx_kernel(const int* __restrict__ p, int nwords) {
    __shared__ int any;
    if (threadIdx.x == 0) any = 0;
    __syncthreads();
    int found = 0;
    for (int i = threadIdx.x; 2 * i + 1 < nwords; i += blockDim.x)
        found |= (p[2 * i + 1] != 0);
    if (found) atomicOr(&any, 1);
    __syncthreads();
    if (threadIdx.x == 0) g_is64 = (any == 0) ? 1 : 0;
}

// fp32 -> fp16, vectorized (n divisible by 4)
__global__ void tofp16v4_kernel(const float4* __restrict__ x, __half2* __restrict__ y, long n4) {
    long i = (long)blockIdx.x * blockDim.x + threadIdx.x;
    if (i >= n4) return;
    float4 v = x[i];
    y[2 * i]     = __floats2half2_rn(v.x, v.y);
    y[2 * i + 1] = __floats2half2_rn(v.z, v.w);
}

// conv_w [o,c,k] -> cwt [k*DD+o][c] fp16, half2 stores
__global__ void transpose_cw_kernel(const float* __restrict__ cw, __half2* __restrict__ th2) {
    int idx = blockIdx.x * blockDim.x + threadIdx.x;   // over DD*DD/2
    if (idx >= DD * (DD / 2)) return;
    int o = idx / (DD / 2), c2 = idx % (DD / 2);
    const float* s0 = cw + ((long)o * DD + 2 * c2) * WW;
    const float* s1 = s0 + WW;
#pragma unroll
    for (int k = 0; k < WW; k++)
        th2[((long)k * DD + o) * (DD / 2) + c2] = __floats2half2_rn(s0[k], s1[k]);
}

// shifted cumsum of G (fp16, fp32 accum) + relu -> fp16, half2 vectorized
__global__ void cumsum_relu_kernel(const __half2* __restrict__ G2, __half2* __restrict__ ch2) {
    long id = (long)blockIdx.x * blockDim.x + threadIdx.x;   // over BL*DD/2
    if (id >= (long)BL * (DD / 2)) return;
    int o2 = (int)(id % (DD / 2));
    int bl = (int)(id / (DD / 2));
    int l  = bl % LL;
    int bt = bl - l;
    float sx = 0.f, sy = 0.f;
#pragma unroll
    for (int k = 0; k < WW; k++) {
        int t = l + k;
        if (t < LL) {
            float2 g = __half22float2(G2[((long)(bt + t) * WW + k) * (DD / 2) + o2]);
            sx += g.x; sy += g.y;
        }
        ch2[((long)bl * WW + k) * (DD / 2) + o2] =
            __floats2half2_rn(fmaxf(sx, 0.f), fmaxf(sy, 0.f));
    }
}

// ---------------------------------------------------------------------------
// fp16 GEMM via mma.sync:  C[m,n] = sum_k A[m,k]*B[n,k]   (fp32 acc)
// CTA tile 128x256, BK=32, 8 warps (2M x 4N), warp tile 64x64.
// 3-stage cp.async pipeline; one __syncthreads per K-iter. 1 CTA/SM.
// EPI: 0=fp32 store, 1=bias+relu->fp16, 2=final fused fp32, 3=plain fp16 store
// blockIdx.z==1 switches to (A2,B2,C2) — used to batch SA/SB in one launch.
#define ROWB 80
#define ATILE (128*ROWB)        // 10240
#define BTILE (256*ROWB)        // 20480
#define STAGEB (ATILE+BTILE)    // 30720
#define NSTG 3
#define SMEMB (NSTG*STAGEB)     // 92160

template <int EPI>
__global__ __launch_bounds__(256, 1)
void gemm_mma(const __half* __restrict__ Ap, int lda,
              const __half* __restrict__ Bp, int ldb,
              float* __restrict__ Cp, __half* __restrict__ Cf16,
              int ldc, int K,
              const float* __restrict__ bias,
              const float* __restrict__ SA, const float* __restrict__ SB,
              const int* __restrict__ span32,
              const __half* A2, const __half* B2, float* C2) {
    extern __shared__ char smem[];
    const uint32_t sbase = smem_u32(smem);
    const int tid = threadIdx.x, lane = tid & 31, wid = tid >> 5;
    const int wm = wid & 1, wn = wid >> 1;           // 2 x 4 warp grid
    const int m0 = blockIdx.y * 128, n0 = blockIdx.x * 256;
    const int NIT = K >> 5;

    const __half* A = Ap;
    const __half* B = Bp;
    float* C = Cp;
    if (blockIdx.z) { A = A2; B = B2; C = C2; }

    const char* gA = (const char*)(A + (long)m0 * lda);
    const char* gB = (const char*)(B + (long)n0 * ldb);
    const long ldaB = (long)lda * 2, ldbB = (long)ldb * 2;

    auto issue_load = [&](int it) {
        const int k0b = it << 6;                     // it*32 cols * 2B
        const uint32_t st = sbase + (it % NSTG) * STAGEB;
#pragma unroll
        for (int i = 0; i < 2; i++) {                // A: 512 chunks
            int s = tid + i * 256;
            int r = s >> 2, kc = s & 3;
            cp16(st + r * ROWB + kc * 16, gA + (long)r * ldaB + k0b + kc * 16);
        }
#pragma unroll
        for (int i = 0; i < 4; i++) {                // B: 1024 chunks
            int s = tid + i * 256;
            int r = s >> 2, kc = s & 3;
            cp16(st + ATILE + r * ROWB + kc * 16, gB + (long)r * ldbB + k0b + kc * 16);
        }
    };

    float acc[4][8][4];
#pragma unroll
    for (int i = 0; i < 4; i++)
#pragma unroll
        for (int j = 0; j < 8; j++)
#pragma unroll
            for (int v = 0; v < 4; v++) acc[i][j][v] = 0.f;

    issue_load(0); CP_COMMIT();
    issue_load(1); CP_COMMIT();

    const uint32_t a_lane_off = (uint32_t)((wm * 64 + (lane & 15)) * ROWB + (lane >> 4) * 16);
    const uint32_t b_lane_off = (uint32_t)((wn * 64 + (lane & 15)) * ROWB + (lane >> 4) * 16);

    for (int it = 0; it < NIT; it++) {
        CP_WAIT1();
        __syncthreads();

        const uint32_t st = sbase + (it % NSTG) * STAGEB;
#pragma unroll
        for (int ks = 0; ks < 2; ks++) {
            uint32_t a[4][4];
#pragma unroll
            for (int mt = 0; mt < 4; mt++)
                LDSM4(a[mt], st + a_lane_off + mt * 16 * ROWB + ks * 32);
            uint32_t b[4][4];
#pragma unroll
            for (int nb = 0; nb < 4; nb++)
                LDSM4(b[nb], st + ATILE + b_lane_off + nb * 16 * ROWB + ks * 32);
#pragma unroll
            for (int mt = 0; mt < 4; mt++)
#pragma unroll
                for (int nt = 0; nt < 8; nt++) {
                    const int nb = nt >> 1, sel = nt & 1;
                    MMA16816(acc[mt][nt], a[mt], b[nb][sel], b[nb][sel + 2]);
                }
        }
        if (it + 2 < NIT) issue_load(it + 2);
        CP_COMMIT();
    }

    // ---- epilogue ----
    const int qrow = lane >> 2, qcol = (lane & 3) * 2;
    const int is64 = (EPI == 2) ? g_is64 : 0;

#pragma unroll
    for (int mt = 0; mt < 4; mt++) {
        const int r0 = m0 + wm * 64 + mt * 16 + qrow;
        const int r1 = r0 + 8;

        const float *sa0 = nullptr, *sb0 = nullptr, *sa1 = nullptr, *sb1 = nullptr;
        if (EPI == 2) {
            int sw0, ew0, sw1, ew1;
            if (is64) {
                sw0 = span32[(long)r0 * 4]; ew0 = span32[(long)r0 * 4 + 2];
                sw1 = span32[(long)r1 * 4]; ew1 = span32[(long)r1 * 4 + 2];
            } else {
                sw0 = span32[(long)r0 * 2]; ew0 = span32[(long)r0 * 2 + 1];
                sw1 = span32[(long)r1 * 2]; ew1 = span32[(long)r1 * 2 + 1];
            }
            sw0 = min(max(sw0, 0), LL - 1); ew0 = min(max(ew0, 0), LL - 1);
            sw1 = min(max(sw1, 0), LL - 1); ew1 = min(max(ew1, 0), LL - 1);
            int boff = (r0 / (LL * WW)) * LL;   // r0, r1 always in same batch (16 | LL*WW)
            sa0 = SA + (long)(boff + sw0) * DD; sb0 = SB + (long)(boff + ew0) * DD;
            sa1 = SA + (long)(boff + sw1) * DD; sb1 = SB + (long)(boff + ew1) * DD;
        }

#pragma unroll
        for (int nt = 0; nt < 8; nt++) {
            const int gc = n0 + wn * 64 + nt * 8 + qcol;
            const float* a = acc[mt][nt];
            if (EPI == 0) {
                *(float2*)(C + (long)r0 * ldc + gc) = make_float2(a[0], a[1]);
                *(float2*)(C + (long)r1 * ldc + gc) = make_float2(a[2], a[3]);
            } else if (EPI == 1) {
                float2 b = *(const float2*)(bias + gc);
                *(__half2*)(Cf16 + (long)r0 * ldc + gc) =
                    __floats2half2_rn(fmaxf(a[0] + b.x, 0.f), fmaxf(a[1] + b.y, 0.f));
                *(__half2*)(Cf16 + (long)r1 * ldc + gc) =
                    __floats2half2_rn(fmaxf(a[2] + b.x, 0.f), fmaxf(a[3] + b.y, 0.f));
            } else if (EPI == 3) {
                *(__half2*)(Cf16 + (long)r0 * ldc + gc) = __floats2half2_rn(a[0], a[1]);
                *(__half2*)(Cf16 + (long)r1 * ldc + gc) = __floats2half2_rn(a[2], a[3]);
            } else {
                float2 b  = *(const float2*)(bias + gc);
                float2 s0 = *(const float2*)(sa0 + gc), e0 = *(const float2*)(sb0 + gc);
                float2 s1 = *(const float2*)(sa1 + gc), e1 = *(const float2*)(sb1 + gc);
                float2 o0 = make_float2(fmaxf(a[0] + s0.x + e0.x + b.x, 0.f),
                                        fmaxf(a[1] + s0.y + e0.y + b.y, 0.f));
                float2 o1 = make_float2(fmaxf(a[2] + s1.x + e1.x + b.x, 0.f),
                                        fmaxf(a[3] + s1.y + e1.y + b.y, 0.f));
                *(float2*)(C + (long)r0 * ldc + gc) = o0;
                *(float2*)(C + (long)r1 * ldc + gc) = o1;
            }
        }
    }
}

// ---------------------------------------------------------------------------
extern "C" void kernel_launch(void* const* d_in, const int* in_sizes, int n_in,
                              void* d_out, int out_size) {
    const float* h      = (const float*)d_in[0];
    const int*   span32 = (const int*)d_in[1];
    const float* proj_w = (const float*)d_in[2];
    const float* proj_b = (const float*)d_in[3];
    const float* conv_w = (const float*)d_in[4];
    const float* out_w  = (const float*)d_in[5];
    const float* out_b  = (const float*)d_in[6];
    float*       out    = (float*)d_out;

    __half *hh, *pwh, *owh, *cwth, *ph, *G, *ch;
    float *SA, *SB;
    cudaGetSymbolAddress((void**)&hh,   g_hh);
    cudaGetSymbolAddress((void**)&pwh,  g_pwh);
    cudaGetSymbolAddress((void**)&owh,  g_owh);
    cudaGetSymbolAddress((void**)&cwth, g_cwth);
    cudaGetSymbolAddress((void**)&ph,   g_ph);
    cudaGetSymbolAddress((void**)&G,    g_G);
    cudaGetSymbolAddress((void**)&ch,   g_ch);
    cudaGetSymbolAddress((void**)&SA,   g_SA);
    cudaGetSymbolAddress((void**)&SB,   g_SB);

    cudaFuncSetAttribute((const void*)gemm_mma<0>, cudaFuncAttributeMaxDynamicSharedMemorySize, SMEMB);
    cudaFuncSetAttribute((const void*)gemm_mma<1>, cudaFuncAttributeMaxDynamicSharedMemorySize, SMEMB);
    cudaFuncSetAttribute((const void*)gemm_mma<2>, cudaFuncAttributeMaxDynamicSharedMemorySize, SMEMB);
    cudaFuncSetAttribute((const void*)gemm_mma<3>, cudaFuncAttributeMaxDynamicSharedMemorySize, SMEMB);

    // 0. span_idx dtype detection (device-side, capturable)
    detect_idx_kernel<<<1, 256>>>(span32, BB * LL * WW * 2);

    // 1. conversions (vectorized)
    tofp16v4_kernel<<<((long)BL * DD / 4 + 255) / 256, 256>>>(
        (const float4*)h, (__half2*)hh, (long)BL * DD / 4);
    tofp16v4_kernel<<<((long)TWOD * DD / 4 + 255) / 256, 256>>>(
        (const float4*)proj_w, (__half2*)pwh, (long)TWOD * DD / 4);
    tofp16v4_kernel<<<((long)DD * THREED / 4 + 255) / 256, 256>>>(
        (const float4*)out_w, (__half2*)owh, (long)DD * THREED / 4);
    transpose_cw_kernel<<<(DD * (DD / 2) + 255) / 256, 256>>>(conv_w, (__half2*)cwth);

    // 2. prelu = relu(h @ proj_w^T + proj_b) -> fp16          [BL, 2D]
    gemm_mma<1><<<dim3(TWOD / 256, BL / 128), 256, SMEMB>>>(
        hh, DD, pwh, DD, nullptr, ph, TWOD, DD, proj_b, nullptr, nullptr, nullptr,
        nullptr, nullptr, nullptr);

    // 3. G = h @ cwt^T -> fp16                                [BL, W*D]
    gemm_mma<3><<<dim3(WD / 256, BL / 128), 256, SMEMB>>>(
        hh, DD, cwth, DD, nullptr, G, WD, DD, nullptr, nullptr, nullptr, nullptr,
        nullptr, nullptr, nullptr);

    // 4+5. SA/SB batched via z: SA = prelu[:,:D]@ow1^T, SB = prelu[:,D:]@ow2^T  [BL, D] each
    gemm_mma<0><<<dim3(DD / 256, BL / 128, 2), 256, SMEMB>>>(
        ph, TWOD, owh, THREED, SA, nullptr, DD, DD, nullptr, nullptr, nullptr, nullptr,
        ph + DD, owh + DD, SB);

    // 6. convrelu = relu(shifted cumsum of G) -> fp16         [M_out, D]
    cumsum_relu_kernel<<<((long)BL * (DD / 2) + 255) / 256, 256>>>(
        (const __half2*)G, (__half2*)ch);

    // 7. out = relu(conv @ out_w[:,2D:]^T + gather(SA) + gather(SB) + out_b)
    gemm_mma<2><<<dim3(DD / 256, MOUT / 128), 256, SMEMB>>>(
        ch, DD, owh + TWOD, THREED, out, nullptr, DD, DD,
        out_b, SA, SB, span32, nullptr, nullptr, nullptr);
}

// round 12
// speedup vs baseline: 2.5368x; 1.1388x over previous
#include <cuda_runtime.h>
#include <cuda_fp16.h>
#include <cstdint>

#define BB 4
#define LL 512
#define DD 768
#define WW 12
#define TWOD 1536
#define THREED 2304
#define BL 2048
#define MOUT 24576
#define WD 9216

// ---- scratch (device globals; no allocation allowed) ----
__device__ __align__(16) __half g_hh[(long)BL*DD];                // h fp16
__device__ __align__(16) __half g_pwh[(long)TWOD*DD];             // proj_w fp16
__device__ __align__(16) __half g_owh[(long)DD*THREED];           // out_w fp16
__device__ __align__(16) __half g_cwth[(long)WD*DD];              // conv_w transposed fp16
__device__ __align__(16) __half g_ph[(long)BL*TWOD];              // relu(proj) fp16
__device__ __align__(16) __half g_G[(long)BL*WD];                 // conv contributions fp16
__device__ __align__(16) __half g_ch[(long)MOUT*DD];              // relu(cumsum) fp16
__device__ __align__(16) float  g_SA[(long)BL*DD], g_SB[(long)BL*DD];
__device__ int g_is64;

// ---- PTX helpers (baseline ISA only; valid on compute_103) ----
__device__ __forceinline__ uint32_t smem_u32(const void* p) {
    uint32_t a;
    asm("{ .reg .u64 t; cvta.to.shared.u64 t, %1; cvt.u32.u64 %0, t; }" : "=r"(a) : "l"(p));
    return a;
}
__device__ __forceinline__ void cp16(uint32_t dst, const void* src) {
    asm volatile("cp.async.cg.shared.global [%0], [%1], 16;" :: "r"(dst), "l"(src));
}
#define CP_COMMIT() asm volatile("cp.async.commit_group;" ::: "memory")
#define CP_WAIT1()  asm volatile("cp.async.wait_group 1;" ::: "memory")

#define LDSM4(r, addr) \
    asm volatile("ldmatrix.sync.aligned.m8n8.x4.shared.b16 {%0,%1,%2,%3}, [%4];" \
        : "=r"((r)[0]), "=r"((r)[1]), "=r"((r)[2]), "=r"((r)[3]) : "r"(addr))

#define MMA16816(acc, a, b0, b1) \
    asm volatile("mma.sync.aligned.m16n8k16.row.col.f32.f16.f16.f32 " \
        "{%0,%1,%2,%3}, {%4,%5,%6,%7}, {%8,%9}, {%0,%1,%2,%3};" \
        : "+f"((acc)[0]), "+f"((acc)[1]), "+f"((acc)[2]), "+f"((acc)[3]) \
        : "r"((a)[0]), "r"((a)[1]), "r"((a)[2]), "r"((a)[3]), "r"(b0), "r"(b1))

// ---------------------------------------------------------------------------
__global__ void detect_idx_kernel(const int* __restrict__ p, int nwords) {
    __shared__ int any;
    if (threadIdx.x == 0) any = 0;
    __syncthreads();
    int found = 0;
    for (int i = threadIdx.x; 2 * i + 1 < nwords; i += blockDim.x)
        found |= (p[2 * i + 1] != 0);
    if (found) atomicOr(&any, 1);
    __syncthreads();
    if (threadIdx.x == 0) g_is64 = (any == 0) ? 1 : 0;
}

// fp32 -> fp16, vectorized (n divisible by 4)
__global__ void tofp16v4_kernel(const float4* __restrict__ x, __half2* __restrict__ y, long n4) {
    long i = (long)blockIdx.x * blockDim.x + threadIdx.x;
    if (i >= n4) return;
    float4 v = x[i];
    y[2 * i]     = __floats2half2_rn(v.x, v.y);
    y[2 * i + 1] = __floats2half2_rn(v.z, v.w);
}

// conv_w [o,c,k] -> cwt [k*DD+o][c] fp16, half2 stores
__global__ void transpose_cw_kernel(const float* __restrict__ cw, __half2* __restrict__ th2) {
    int idx = blockIdx.x * blockDim.x + threadIdx.x;   // over DD*DD/2
    if (idx >= DD * (DD / 2)) return;
    int o = idx / (DD / 2), c2 = idx % (DD / 2);
    const float* s0 = cw + ((long)o * DD + 2 * c2) * WW;
    const float* s1 = s0 + WW;
#pragma unroll
    for (int k = 0; k < WW; k++)
        th2[((long)k * DD + o) * (DD / 2) + c2] = __floats2half2_rn(s0[k], s1[k]);
}

// shifted cumsum of G (fp16, fp32 accum) + relu -> fp16, half2 vectorized
__global__ void cumsum_relu_kernel(const __half2* __restrict__ G2, __half2* __restrict__ ch2) {
    long id = (long)blockIdx.x * blockDim.x + threadIdx.x;   // over BL*DD/2
    if (id >= (long)BL * (DD / 2)) return;
    int o2 = (int)(id % (DD / 2));
    int bl = (int)(id / (DD / 2));
    int l  = bl % LL;
    int bt = bl - l;
    float sx = 0.f, sy = 0.f;
#pragma unroll
    for (int k = 0; k < WW; k++) {
        int t = l + k;
        if (t < LL) {
            float2 g = __half22float2(G2[((long)(bt + t) * WW + k) * (DD / 2) + o2]);
            sx += g.x; sy += g.y;
        }
        ch2[((long)bl * WW + k) * (DD / 2) + o2] =
            __floats2half2_rn(fmaxf(sx, 0.f), fmaxf(sy, 0.f));
    }
}

// ---------------------------------------------------------------------------
// fp16 GEMM via mma.sync:  C[m,n] = sum_k A[m,k]*B[n,k]   (fp32 acc)
// CTA tile 128x256, BK=32, 8 warps (2M x 4N), warp tile 64x64.
// 3-stage cp.async pipeline; one __syncthreads per K-iter.
// EPI: 0=fp32 store, 1=bias+relu->fp16, 2=final fused fp32, 3=plain fp16 store
// blockIdx.z==1 switches to (A2,B2,C2) — used to batch SA/SB in one launch.
#define ROWB 80
#define ATILE (128*ROWB)        // 10240
#define BTILE (256*ROWB)        // 20480
#define STAGEB (ATILE+BTILE)    // 30720
#define NSTG 3
#define SMEMB (NSTG*STAGEB)     // 92160

template <int EPI>
__global__ __launch_bounds__(256, 1)
void gemm_mma(const __half* __restrict__ Ap, int lda,
              const __half* __restrict__ Bp, int ldb,
              float* __restrict__ Cp, __half* __restrict__ Cf16,
              int ldc, int K,
              const float* __restrict__ bias,
              const float* __restrict__ SA, const float* __restrict__ SB,
              const int* __restrict__ span32,
              const __half* A2, const __half* B2, float* C2) {
    extern __shared__ char smem[];
    const uint32_t sbase = smem_u32(smem);
    const int tid = threadIdx.x, lane = tid & 31, wid = tid >> 5;
    const int wm = wid & 1, wn = wid >> 1;           // 2 x 4 warp grid
    const int m0 = blockIdx.y * 128, n0 = blockIdx.x * 256;
    const int NIT = K >> 5;

    const __half* A = Ap;
    const __half* B = Bp;
    float* C = Cp;
    if (blockIdx.z) { A = A2; B = B2; C = C2; }

    const char* gA = (const char*)(A + (long)m0 * lda);
    const char* gB = (const char*)(B + (long)n0 * ldb);
    const long ldaB = (long)lda * 2, ldbB = (long)ldb * 2;

    auto issue_load = [&](int it) {
        const int k0b = it << 6;                     // it*32 cols * 2B
        const uint32_t st = sbase + (it % NSTG) * STAGEB;
#pragma unroll
        for (int i = 0; i < 2; i++) {                // A: 512 chunks
            int s = tid + i * 256;
            int r = s >> 2, kc = s & 3;
            cp16(st + r * ROWB + kc * 16, gA + (long)r * ldaB + k0b + kc * 16);
        }
#pragma unroll
        for (int i = 0; i < 4; i++) {                // B: 1024 chunks
            int s = tid + i * 256;
            int r = s >> 2, kc = s & 3;
            cp16(st + ATILE + r * ROWB + kc * 16, gB + (long)r * ldbB + k0b + kc * 16);
        }
    };

    float acc[4][8][4];
#pragma unroll
    for (int i = 0; i < 4; i++)
#pragma unroll
        for (int j = 0; j < 8; j++)
#pragma unroll
            for (int v = 0; v < 4; v++) acc[i][j][v] = 0.f;

    issue_load(0); CP_COMMIT();
    issue_load(1); CP_COMMIT();

    const uint32_t a_lane_off = (uint32_t)((wm * 64 + (lane & 15)) * ROWB + (lane >> 4) * 16);
    const uint32_t b_lane_off = (uint32_t)((wn * 64 + (lane & 15)) * ROWB + (lane >> 4) * 16);

    for (int it = 0; it < NIT; it++) {
        CP_WAIT1();
        __syncthreads();

        const uint32_t st = sbase + (it % NSTG) * STAGEB;
#pragma unroll
        for (int ks = 0; ks < 2; ks++) {
            uint32_t a[4][4];
#pragma unroll
            for (int mt = 0; mt < 4; mt++)
                LDSM4(a[mt], st + a_lane_off + mt * 16 * ROWB + ks * 32);
            uint32_t b[4][4];
#pragma unroll
            for (int nb = 0; nb < 4; nb++)
                LDSM4(b[nb], st + ATILE + b_lane_off + nb * 16 * ROWB + ks * 32);
#pragma unroll
            for (int mt = 0; mt < 4; mt++)
#pragma unroll
                for (int nt = 0; nt < 8; nt++) {
                    const int nb = nt >> 1, sel = nt & 1;
                    MMA16816(acc[mt][nt], a[mt], b[nb][sel], b[nb][sel + 2]);
                }
        }
        if (it + 2 < NIT) issue_load(it + 2);
        CP_COMMIT();
    }

    // ---- epilogue ----
    const int qrow = lane >> 2, qcol = (lane & 3) * 2;
    const int is64 = (EPI == 2) ? g_is64 : 0;

#pragma unroll
    for (int mt = 0; mt < 4; mt++) {
        const int r0 = m0 + wm * 64 + mt * 16 + qrow;
        const int r1 = r0 + 8;

        const float *sa0 = nullptr, *sb0 = nullptr, *sa1 = nullptr, *sb1 = nullptr;
        if (EPI == 2) {
            int sw0, ew0, sw1, ew1;
            if (is64) {
                sw0 = span32[(long)r0 * 4]; ew0 = span32[(long)r0 * 4 + 2];
                sw1 = span32[(long)r1 * 4]; ew1 = span32[(long)r1 * 4 + 2];
            } else {
                sw0 = span32[(long)r0 * 2]; ew0 = span32[(long)r0 * 2 + 1];
                sw1 = span32[(long)r1 * 2]; ew1 = span32[(long)r1 * 2 + 1];
            }
            sw0 = min(max(sw0, 0), LL - 1); ew0 = min(max(ew0, 0), LL - 1);
            sw1 = min(max(sw1, 0), LL - 1); ew1 = min(max(ew1, 0), LL - 1);
            int boff = (r0 / (LL * WW)) * LL;   // r0, r1 always in same batch (16 | LL*WW)
            sa0 = SA + (long)(boff + sw0) * DD; sb0 = SB + (long)(boff + ew0) * DD;
            sa1 = SA + (long)(boff + sw1) * DD; sb1 = SB + (long)(boff + ew1) * DD;
        }

#pragma unroll
        for (int nt = 0; nt < 8; nt++) {
            const int gc = n0 + wn * 64 + nt * 8 + qcol;
            const float* a = acc[mt][nt];
            if (EPI == 0) {
                *(float2*)(C + (long)r0 * ldc + gc) = make_float2(a[0], a[1]);
                *(float2*)(C + (long)r1 * ldc + gc) = make_float2(a[2], a[3]);
            } else if (EPI == 1) {
                float2 b = *(const float2*)(bias + gc);
                *(__half2*)(Cf16 + (long)r0 * ldc + gc) =
                    __floats2half2_rn(fmaxf(a[0] + b.x, 0.f), fmaxf(a[1] + b.y, 0.f));
                *(__half2*)(Cf16 + (long)r1 * ldc + gc) =
                    __floats2half2_rn(fmaxf(a[2] + b.x, 0.f), fmaxf(a[3] + b.y, 0.f));
            } else if (EPI == 3) {
                *(__half2*)(Cf16 + (long)r0 * ldc + gc) = __floats2half2_rn(a[0], a[1]);
                *(__half2*)(Cf16 + (long)r1 * ldc + gc) = __floats2half2_rn(a[2], a[3]);
            } else {
                float2 b  = *(const float2*)(bias + gc);
                float2 s0 = *(const float2*)(sa0 + gc), e0 = *(const float2*)(sb0 + gc);
                float2 s1 = *(const float2*)(sa1 + gc), e1 = *(const float2*)(sb1 + gc);
                float2 o0 = make_float2(fmaxf(a[0] + s0.x + e0.x + b.x, 0.f),
                                        fmaxf(a[1] + s0.y + e0.y + b.y, 0.f));
                float2 o1 = make_float2(fmaxf(a[2] + s1.x + e1.x + b.x, 0.f),
                                        fmaxf(a[3] + s1.y + e1.y + b.y, 0.f));
                *(float2*)(C + (long)r0 * ldc + gc) = o0;
                *(float2*)(C + (long)r1 * ldc + gc) = o1;
            }
        }
    }
}

// ---------------------------------------------------------------------------
extern "C" void kernel_launch(void* const* d_in, const int* in_sizes, int n_in,
                              void* d_out, int out_size) {
    const float* h      = (const float*)d_in[0];
    const int*   span32 = (const int*)d_in[1];
    const float* proj_w = (const float*)d_in[2];
    const float* proj_b = (const float*)d_in[3];
    const float* conv_w = (const float*)d_in[4];
    const float* out_w  = (const float*)d_in[5];
    const float* out_b  = (const float*)d_in[6];
    float*       out    = (float*)d_out;

    __half *hh, *pwh, *owh, *cwth, *ph, *G, *ch;
    float *SA, *SB;
    cudaGetSymbolAddress((void**)&hh,   g_hh);
    cudaGetSymbolAddress((void**)&pwh,  g_pwh);
    cudaGetSymbolAddress((void**)&owh,  g_owh);
    cudaGetSymbolAddress((void**)&cwth, g_cwth);
    cudaGetSymbolAddress((void**)&ph,   g_ph);
    cudaGetSymbolAddress((void**)&G,    g_G);
    cudaGetSymbolAddress((void**)&ch,   g_ch);
    cudaGetSymbolAddress((void**)&SA,   g_SA);
    cudaGetSymbolAddress((void**)&SB,   g_SB);

    cudaFuncSetAttribute((const void*)gemm_mma<0>, cudaFuncAttributeMaxDynamicSharedMemorySize, SMEMB);
    cudaFuncSetAttribute((const void*)gemm_mma<1>, cudaFuncAttributeMaxDynamicSharedMemorySize, SMEMB);
    cudaFuncSetAttribute((const void*)gemm_mma<2>, cudaFuncAttributeMaxDynamicSharedMemorySize, SMEMB);
    cudaFuncSetAttribute((const void*)gemm_mma<3>, cudaFuncAttributeMaxDynamicSharedMemorySize, SMEMB);

    // ---- side stream + fork/join events (host-side handles only; created
    // once; identical captured work every call) ----
    static cudaStream_t s1 = nullptr;
    static cudaEvent_t evFork = nullptr, evJoin = nullptr;
    static bool tried = false;
    if (!tried) {
        tried = true;
        if (cudaStreamCreateWithFlags(&s1, cudaStreamNonBlocking) != cudaSuccess) s1 = nullptr;
        if (cudaEventCreateWithFlags(&evFork, cudaEventDisableTiming) != cudaSuccess) evFork = nullptr;
        if (cudaEventCreateWithFlags(&evJoin, cudaEventDisableTiming) != cudaSuccess) evJoin = nullptr;
    }
    const bool fork = (s1 && evFork && evJoin);
    cudaStream_t sB = fork ? s1 : (cudaStream_t)0;   // branch-B stream

    // ---- branch-independent prologue (main stream): hh = fp16(h) ----
    tofp16v4_kernel<<<((long)BL * DD / 4 + 255) / 256, 256>>>(
        (const float4*)h, (__half2*)hh, (long)BL * DD / 4);

    if (fork) {
        cudaEventRecord(evFork, 0);
        cudaStreamWaitEvent(s1, evFork, 0);
    }

    // ---- branch A (main): conv path ----
    transpose_cw_kernel<<<(DD * (DD / 2) + 255) / 256, 256>>>(conv_w, (__half2*)cwth);
    gemm_mma<3><<<dim3(WD / 256, BL / 128), 256, SMEMB>>>(          // G = h @ cwt^T
        hh, DD, cwth, DD, nullptr, G, WD, DD, nullptr, nullptr, nullptr, nullptr,
        nullptr, nullptr, nullptr);
    cumsum_relu_kernel<<<((long)BL * (DD / 2) + 255) / 256, 256>>>( // ch = relu(cumsum(G))
        (const __half2*)G, (__half2*)ch);

    // ---- branch B (s1): span-rep path ----
    detect_idx_kernel<<<1, 256, 0, sB>>>(span32, BB * LL * WW * 2);
    tofp16v4_kernel<<<((long)TWOD * DD / 4 + 255) / 256, 256, 0, sB>>>(
        (const float4*)proj_w, (__half2*)pwh, (long)TWOD * DD / 4);
    tofp16v4_kernel<<<((long)DD * THREED / 4 + 255) / 256, 256, 0, sB>>>(
        (const float4*)out_w, (__half2*)owh, (long)DD * THREED / 4);
    gemm_mma<1><<<dim3(TWOD / 256, BL / 128), 256, SMEMB, sB>>>(    // prelu
        hh, DD, pwh, DD, nullptr, ph, TWOD, DD, proj_b, nullptr, nullptr, nullptr,
        nullptr, nullptr, nullptr);
    gemm_mma<0><<<dim3(DD / 256, BL / 128, 2), 256, SMEMB, sB>>>(   // SA / SB batched
        ph, TWOD, owh, THREED, SA, nullptr, DD, DD, nullptr, nullptr, nullptr, nullptr,
        ph + DD, owh + DD, SB);

    if (fork) {
        cudaEventRecord(evJoin, s1);
        cudaStreamWaitEvent(0, evJoin, 0);
    }

    // ---- final fused GEMM (main) ----
    gemm_mma<2><<<dim3(DD / 256, MOUT / 128), 256, SMEMB>>>(
        ch, DD, owh + TWOD, THREED, out, nullptr, DD, DD,
        out_b, SA, SB, span32, nullptr, nullptr, nullptr);
}

// round 13
// speedup vs baseline: 2.8801x; 1.1353x over previous
#include <cuda_runtime.h>
#include <cuda_fp16.h>
#include <cstdint>

#define BB 4
#define LL 512
#define DD 768
#define WW 12
#define TWOD 1536
#define THREED 2304
#define BL 2048
#define MOUT 24576
#define WD 9216

// ---- scratch (device globals; no allocation allowed) ----
__device__ __align__(16) __half g_hh[(long)BL*DD];                // h fp16
__device__ __align__(16) __half g_pwh[(long)TWOD*DD];             // proj_w fp16
__device__ __align__(16) __half g_owh[(long)DD*THREED];           // out_w fp16
__device__ __align__(16) __half g_cwth[(long)WD*DD];              // conv_w transposed fp16
__device__ __align__(16) __half g_ph[(long)BL*TWOD];              // relu(proj) fp16
__device__ __align__(16) __half g_G[(long)BL*WD];                 // conv contributions fp16
__device__ __align__(16) __half g_ch[(long)MOUT*DD];              // relu(cumsum) fp16
__device__ __align__(16) float  g_SA[(long)BL*DD], g_SB[(long)BL*DD];
__device__ int g_is64;

// ---- PTX helpers (baseline ISA only; valid on compute_103) ----
__device__ __forceinline__ uint32_t smem_u32(const void* p) {
    uint32_t a;
    asm("{ .reg .u64 t; cvta.to.shared.u64 t, %1; cvt.u32.u64 %0, t; }" : "=r"(a) : "l"(p));
    return a;
}
__device__ __forceinline__ void cp16(uint32_t dst, const void* src) {
    asm volatile("cp.async.cg.shared.global [%0], [%1], 16;" :: "r"(dst), "l"(src));
}
#define CP_COMMIT() asm volatile("cp.async.commit_group;" ::: "memory")
#define CP_WAIT1()  asm volatile("cp.async.wait_group 1;" ::: "memory")

#define LDSM4(r, addr) \
    asm volatile("ldmatrix.sync.aligned.m8n8.x4.shared.b16 {%0,%1,%2,%3}, [%4];" \
        : "=r"((r)[0]), "=r"((r)[1]), "=r"((r)[2]), "=r"((r)[3]) : "r"(addr))

#define MMA16816(acc, a, b0, b1) \
    asm volatile("mma.sync.aligned.m16n8k16.row.col.f32.f16.f16.f32 " \
        "{%0,%1,%2,%3}, {%4,%5,%6,%7}, {%8,%9}, {%0,%1,%2,%3};" \
        : "+f"((acc)[0]), "+f"((acc)[1]), "+f"((acc)[2]), "+f"((acc)[3]) \
        : "r"((a)[0]), "r"((a)[1]), "r"((a)[2]), "r"((a)[3]), "r"(b0), "r"(b1))

// ---------------------------------------------------------------------------
__global__ void detect_idx_kernel(const int* __restrict__ p, int nwords) {
    __shared__ int any;
    if (threadIdx.x == 0) any = 0;
    __syncthreads();
    int found = 0;
    for (int i = threadIdx.x; 2 * i + 1 < nwords; i += blockDim.x)
        found |= (p[2 * i + 1] != 0);
    if (found) atomicOr(&any, 1);
    __syncthreads();
    if (threadIdx.x == 0) g_is64 = (any == 0) ? 1 : 0;
}

// fp32 -> fp16, vectorized (n divisible by 4)
__global__ void tofp16v4_kernel(const float4* __restrict__ x, __half2* __restrict__ y, long n4) {
    long i = (long)blockIdx.x * blockDim.x + threadIdx.x;
    if (i >= n4) return;
    float4 v = x[i];
    y[2 * i]     = __floats2half2_rn(v.x, v.y);
    y[2 * i + 1] = __floats2half2_rn(v.z, v.w);
}

// conv_w [o,c,k] -> cwt [k*DD+o][c] fp16, half2 stores
__global__ void transpose_cw_kernel(const float* __restrict__ cw, __half2* __restrict__ th2) {
    int idx = blockIdx.x * blockDim.x + threadIdx.x;   // over DD*DD/2
    if (idx >= DD * (DD / 2)) return;
    int o = idx / (DD / 2), c2 = idx % (DD / 2);
    const float* s0 = cw + ((long)o * DD + 2 * c2) * WW;
    const float* s1 = s0 + WW;
#pragma unroll
    for (int k = 0; k < WW; k++)
        th2[((long)k * DD + o) * (DD / 2) + c2] = __floats2half2_rn(s0[k], s1[k]);
}

// shifted cumsum of G (fp16, fp32 accum) + relu -> fp16, half2 vectorized
__global__ void cumsum_relu_kernel(const __half2* __restrict__ G2, __half2* __restrict__ ch2) {
    long id = (long)blockIdx.x * blockDim.x + threadIdx.x;   // over BL*DD/2
    if (id >= (long)BL * (DD / 2)) return;
    int o2 = (int)(id % (DD / 2));
    int bl = (int)(id / (DD / 2));
    int l  = bl % LL;
    int bt = bl - l;
    float sx = 0.f, sy = 0.f;
#pragma unroll
    for (int k = 0; k < WW; k++) {
        int t = l + k;
        if (t < LL) {
            float2 g = __half22float2(G2[((long)(bt + t) * WW + k) * (DD / 2) + o2]);
            sx += g.x; sy += g.y;
        }
        ch2[((long)bl * WW + k) * (DD / 2) + o2] =
            __floats2half2_rn(fmaxf(sx, 0.f), fmaxf(sy, 0.f));
    }
}

// ---------------------------------------------------------------------------
// fp16 GEMM via mma.sync:  C[m,n] = sum_k A[m,k]*B[n,k]   (fp32 acc)
// CTA tile 128x128, BK=64, 8 warps (2M x 4N), warp tile 64x32.
// 2-stage double buffer, 2 syncs/iter, 64 MMAs per sync interval. 2 CTAs/SM.
// EPI: 0=fp32 store, 1=bias+relu->fp16, 2=final fused fp32, 3=plain fp16 store
// blockIdx.z==1 switches to (A2,B2,C2) — used to batch SA/SB in one launch.
#define ROWB 144
#define TILEB (128*ROWB)        // 18432
#define STAGEB (2*TILEB)        // 36864 (A + B)
#define SMEMB (2*STAGEB)        // 73728

template <int EPI>
__global__ __launch_bounds__(256, 2)
void gemm_mma(const __half* __restrict__ Ap, int lda,
              const __half* __restrict__ Bp, int ldb,
              float* __restrict__ Cp, __half* __restrict__ Cf16,
              int ldc, int K,
              const float* __restrict__ bias,
              const float* __restrict__ SA, const float* __restrict__ SB,
              const int* __restrict__ span32,
              const __half* A2, const __half* B2, float* C2) {
    extern __shared__ char smem[];
    const uint32_t sbase = smem_u32(smem);
    const int tid = threadIdx.x, lane = tid & 31, wid = tid >> 5;
    const int wm = wid & 1, wn = wid >> 1;           // 2 x 4 warp grid
    const int m0 = blockIdx.y * 128, n0 = blockIdx.x * 128;
    const int NIT = K >> 6;                          // BK = 64

    const __half* A = Ap;
    const __half* B = Bp;
    float* C = Cp;
    if (blockIdx.z) { A = A2; B = B2; C = C2; }

    const char* gA = (const char*)(A + (long)m0 * lda);
    const char* gB = (const char*)(B + (long)n0 * ldb);
    const long ldaB = (long)lda * 2, ldbB = (long)ldb * 2;

    // per stage: A tile 128 rows x 128B (8 chunks) = 1024 chunks; B same.
    auto issue_load = [&](int it) {
        const int k0b = it << 7;                     // it*64 cols * 2B
        const uint32_t st = sbase + (it & 1) * STAGEB;
#pragma unroll
        for (int i = 0; i < 4; i++) {                // A
            int s = tid + i * 256;
            int r = s >> 3, kc = s & 7;
            cp16(st + r * ROWB + kc * 16, gA + (long)r * ldaB + k0b + kc * 16);
        }
#pragma unroll
        for (int i = 0; i < 4; i++) {                // B
            int s = tid + i * 256;
            int r = s >> 3, kc = s & 7;
            cp16(st + TILEB + r * ROWB + kc * 16, gB + (long)r * ldbB + k0b + kc * 16);
        }
    };

    float acc[4][4][4];
#pragma unroll
    for (int i = 0; i < 4; i++)
#pragma unroll
        for (int j = 0; j < 4; j++)
#pragma unroll
            for (int v = 0; v < 4; v++) acc[i][j][v] = 0.f;

    issue_load(0); CP_COMMIT();

    const uint32_t a_lane_off = (uint32_t)((wm * 64 + (lane & 15)) * ROWB + (lane >> 4) * 16);
    const uint32_t b_lane_off = (uint32_t)((wn * 32 + (lane & 15)) * ROWB + (lane >> 4) * 16);

    for (int it = 0; it < NIT; it++) {
        if (it + 1 < NIT) issue_load(it + 1);
        CP_COMMIT();
        CP_WAIT1();
        __syncthreads();

        const uint32_t st = sbase + (it & 1) * STAGEB;
#pragma unroll
        for (int ks = 0; ks < 4; ks++) {
            uint32_t a[4][4];
#pragma unroll
            for (int mt = 0; mt < 4; mt++)
                LDSM4(a[mt], st + a_lane_off + mt * 16 * ROWB + ks * 32);
            uint32_t b[2][4];
#pragma unroll
            for (int nb = 0; nb < 2; nb++)
                LDSM4(b[nb], st + TILEB + b_lane_off + nb * 16 * ROWB + ks * 32);
#pragma unroll
            for (int mt = 0; mt < 4; mt++)
#pragma unroll
                for (int nt = 0; nt < 4; nt++) {
                    const int nb = nt >> 1, sel = nt & 1;
                    MMA16816(acc[mt][nt], a[mt], b[nb][sel], b[nb][sel + 2]);
                }
        }
        __syncthreads();
    }

    // ---- epilogue ----
    const int qrow = lane >> 2, qcol = (lane & 3) * 2;
    const int is64 = (EPI == 2) ? g_is64 : 0;

#pragma unroll
    for (int mt = 0; mt < 4; mt++) {
        const int r0 = m0 + wm * 64 + mt * 16 + qrow;
        const int r1 = r0 + 8;

        const float *sa0 = nullptr, *sb0 = nullptr, *sa1 = nullptr, *sb1 = nullptr;
        if (EPI == 2) {
            int sw0, ew0, sw1, ew1;
            if (is64) {
                sw0 = span32[(long)r0 * 4]; ew0 = span32[(long)r0 * 4 + 2];
                sw1 = span32[(long)r1 * 4]; ew1 = span32[(long)r1 * 4 + 2];
            } else {
                sw0 = span32[(long)r0 * 2]; ew0 = span32[(long)r0 * 2 + 1];
                sw1 = span32[(long)r1 * 2]; ew1 = span32[(long)r1 * 2 + 1];
            }
            sw0 = min(max(sw0, 0), LL - 1); ew0 = min(max(ew0, 0), LL - 1);
            sw1 = min(max(sw1, 0), LL - 1); ew1 = min(max(ew1, 0), LL - 1);
            int boff = (r0 / (LL * WW)) * LL;   // r0, r1 always in same batch (16 | LL*WW)
            sa0 = SA + (long)(boff + sw0) * DD; sb0 = SB + (long)(boff + ew0) * DD;
            sa1 = SA + (long)(boff + sw1) * DD; sb1 = SB + (long)(boff + ew1) * DD;
        }

#pragma unroll
        for (int nt = 0; nt < 4; nt++) {
            const int gc = n0 + wn * 32 + nt * 8 + qcol;
            const float* a = acc[mt][nt];
            if (EPI == 0) {
                *(float2*)(C + (long)r0 * ldc + gc) = make_float2(a[0], a[1]);
                *(float2*)(C + (long)r1 * ldc + gc) = make_float2(a[2], a[3]);
            } else if (EPI == 1) {
                float2 b = *(const float2*)(bias + gc);
                *(__half2*)(Cf16 + (long)r0 * ldc + gc) =
                    __floats2half2_rn(fmaxf(a[0] + b.x, 0.f), fmaxf(a[1] + b.y, 0.f));
                *(__half2*)(Cf16 + (long)r1 * ldc + gc) =
                    __floats2half2_rn(fmaxf(a[2] + b.x, 0.f), fmaxf(a[3] + b.y, 0.f));
            } else if (EPI == 3) {
                *(__half2*)(Cf16 + (long)r0 * ldc + gc) = __floats2half2_rn(a[0], a[1]);
                *(__half2*)(Cf16 + (long)r1 * ldc + gc) = __floats2half2_rn(a[2], a[3]);
            } else {
                float2 b  = *(const float2*)(bias + gc);
                float2 s0 = *(const float2*)(sa0 + gc), e0 = *(const float2*)(sb0 + gc);
                float2 s1 = *(const float2*)(sa1 + gc), e1 = *(const float2*)(sb1 + gc);
                float2 o0 = make_float2(fmaxf(a[0] + s0.x + e0.x + b.x, 0.f),
                                        fmaxf(a[1] + s0.y + e0.y + b.y, 0.f));
                float2 o1 = make_float2(fmaxf(a[2] + s1.x + e1.x + b.x, 0.f),
                                        fmaxf(a[3] + s1.y + e1.y + b.y, 0.f));
                *(float2*)(C + (long)r0 * ldc + gc) = o0;
                *(float2*)(C + (long)r1 * ldc + gc) = o1;
            }
        }
    }
}

// ---------------------------------------------------------------------------
extern "C" void kernel_launch(void* const* d_in, const int* in_sizes, int n_in,
                              void* d_out, int out_size) {
    const float* h      = (const float*)d_in[0];
    const int*   span32 = (const int*)d_in[1];
    const float* proj_w = (const float*)d_in[2];
    const float* proj_b = (const float*)d_in[3];
    const float* conv_w = (const float*)d_in[4];
    const float* out_w  = (const float*)d_in[5];
    const float* out_b  = (const float*)d_in[6];
    float*       out    = (float*)d_out;

    __half *hh, *pwh, *owh, *cwth, *ph, *G, *ch;
    float *SA, *SB;
    cudaGetSymbolAddress((void**)&hh,   g_hh);
    cudaGetSymbolAddress((void**)&pwh,  g_pwh);
    cudaGetSymbolAddress((void**)&owh,  g_owh);
    cudaGetSymbolAddress((void**)&cwth, g_cwth);
    cudaGetSymbolAddress((void**)&ph,   g_ph);
    cudaGetSymbolAddress((void**)&G,    g_G);
    cudaGetSymbolAddress((void**)&ch,   g_ch);
    cudaGetSymbolAddress((void**)&SA,   g_SA);
    cudaGetSymbolAddress((void**)&SB,   g_SB);

    cudaFuncSetAttribute((const void*)gemm_mma<0>, cudaFuncAttributeMaxDynamicSharedMemorySize, SMEMB);
    cudaFuncSetAttribute((const void*)gemm_mma<1>, cudaFuncAttributeMaxDynamicSharedMemorySize, SMEMB);
    cudaFuncSetAttribute((const void*)gemm_mma<2>, cudaFuncAttributeMaxDynamicSharedMemorySize, SMEMB);
    cudaFuncSetAttribute((const void*)gemm_mma<3>, cudaFuncAttributeMaxDynamicSharedMemorySize, SMEMB);

    // ---- side stream + fork/join events (host-side handles only; created
    // once; identical captured work every call) ----
    static cudaStream_t s1 = nullptr;
    static cudaEvent_t evFork = nullptr, evJoin = nullptr;
    static bool tried = false;
    if (!tried) {
        tried = true;
        if (cudaStreamCreateWithFlags(&s1, cudaStreamNonBlocking) != cudaSuccess) s1 = nullptr;
        if (cudaEventCreateWithFlags(&evFork, cudaEventDisableTiming) != cudaSuccess) evFork = nullptr;
        if (cudaEventCreateWithFlags(&evJoin, cudaEventDisableTiming) != cudaSuccess) evJoin = nullptr;
    }
    const bool fork = (s1 && evFork && evJoin);
    cudaStream_t sB = fork ? s1 : (cudaStream_t)0;   // branch-B stream

    // ---- branch-independent prologue (main stream): hh = fp16(h) ----
    tofp16v4_kernel<<<((long)BL * DD / 4 + 255) / 256, 256>>>(
        (const float4*)h, (__half2*)hh, (long)BL * DD / 4);

    if (fork) {
        cudaEventRecord(evFork, 0);
        cudaStreamWaitEvent(s1, evFork, 0);
    }

    // ---- branch A (main): conv path ----
    transpose_cw_kernel<<<(DD * (DD / 2) + 255) / 256, 256>>>(conv_w, (__half2*)cwth);
    gemm_mma<3><<<dim3(WD / 128, BL / 128), 256, SMEMB>>>(          // G = h @ cwt^T
        hh, DD, cwth, DD, nullptr, G, WD, DD, nullptr, nullptr, nullptr, nullptr,
        nullptr, nullptr, nullptr);
    cumsum_relu_kernel<<<((long)BL * (DD / 2) + 255) / 256, 256>>>( // ch = relu(cumsum(G))
        (const __half2*)G, (__half2*)ch);

    // ---- branch B (s1): span-rep path ----
    detect_idx_kernel<<<1, 256, 0, sB>>>(span32, BB * LL * WW * 2);
    tofp16v4_kernel<<<((long)TWOD * DD / 4 + 255) / 256, 256, 0, sB>>>(
        (const float4*)proj_w, (__half2*)pwh, (long)TWOD * DD / 4);
    tofp16v4_kernel<<<((long)DD * THREED / 4 + 255) / 256, 256, 0, sB>>>(
        (const float4*)out_w, (__half2*)owh, (long)DD * THREED / 4);
    gemm_mma<1><<<dim3(TWOD / 128, BL / 128), 256, SMEMB, sB>>>(    // prelu
        hh, DD, pwh, DD, nullptr, ph, TWOD, DD, proj_b, nullptr, nullptr, nullptr,
        nullptr, nullptr, nullptr);
    gemm_mma<0><<<dim3(DD / 128, BL / 128, 2), 256, SMEMB, sB>>>(   // SA / SB batched
        ph, TWOD, owh, THREED, SA, nullptr, DD, DD, nullptr, nullptr, nullptr, nullptr,
        ph + DD, owh + DD, SB);

    if (fork) {
        cudaEventRecord(evJoin, s1);
        cudaStreamWaitEvent(0, evJoin, 0);
    }

    // ---- final fused GEMM (main) ----
    gemm_mma<2><<<dim3(DD / 128, MOUT / 128), 256, SMEMB>>>(
        ch, DD, owh + TWOD, THREED, out, nullptr, DD, DD,
        out_b, SA, SB, span32, nullptr, nullptr, nullptr);
}